// round 1
// baseline (speedup 1.0000x reference)
#include <cuda_runtime.h>
#include <math.h>

// Problem constants
#define Bc   2
#define Sc   2048
#define Dc   2048
#define Hc   16
#define HDc  128
#define ROTc 64
#define Mc   (Bc*Sc)   // 4096 rows in all projections

// ---------------------------------------------------------------------------
// Scratch (no cudaMalloc allowed): 4 x 32MB fp32 buffers + counts
// ---------------------------------------------------------------------------
__device__ float g_q [(size_t)Bc*Sc*Dc];
__device__ float g_k [(size_t)Bc*Sc*Dc];
__device__ float g_v [(size_t)Bc*Sc*Dc];
__device__ float g_ab[(size_t)Bc*Sc*Dc];
__device__ float g_cnt[Bc*Sc];

// ---------------------------------------------------------------------------
// GEMM: C[M,N] = A[M,K] * W[N,K]^T   (all row-major, NT form)
// 128x128 block, K-tile 8, 256 threads, 8x8 per-thread microtile.
// ---------------------------------------------------------------------------
#define GBM 128
#define GBN 128
#define GBK 8

__global__ __launch_bounds__(256) void gemm_nt(
    const float* __restrict__ A, const float* __restrict__ W,
    float* __restrict__ C, int M, int N, int K)
{
    __shared__ float As[GBK][GBM];
    __shared__ float Bs[GBK][GBN];

    const int tid = threadIdx.x;
    const int tx = tid & 15;
    const int ty = tid >> 4;
    const int bm = blockIdx.y * GBM;
    const int bn = blockIdx.x * GBN;

    const float* Ab = A + (size_t)bm * K;
    const float* Wb = W + (size_t)bn * K;

    float acc[8][8];
#pragma unroll
    for (int i = 0; i < 8; i++)
#pragma unroll
        for (int j = 0; j < 8; j++) acc[i][j] = 0.f;

    const int lr = tid >> 1;        // 0..127 row within tile
    const int lc = (tid & 1) * 4;   // 0 or 4 : float4 column group

    for (int kt = 0; kt < K; kt += GBK) {
        float4 av = *(const float4*)(Ab + (size_t)lr * K + kt + lc);
        float4 wv = *(const float4*)(Wb + (size_t)lr * K + kt + lc);
        __syncthreads();   // previous compute done reading smem
        As[lc + 0][lr] = av.x; As[lc + 1][lr] = av.y;
        As[lc + 2][lr] = av.z; As[lc + 3][lr] = av.w;
        Bs[lc + 0][lr] = wv.x; Bs[lc + 1][lr] = wv.y;
        Bs[lc + 2][lr] = wv.z; Bs[lc + 3][lr] = wv.w;
        __syncthreads();

#pragma unroll
        for (int kk = 0; kk < GBK; kk++) {
            float4 a0 = *(const float4*)&As[kk][ty * 8];
            float4 a1 = *(const float4*)&As[kk][ty * 8 + 4];
            float4 b0 = *(const float4*)&Bs[kk][tx * 8];
            float4 b1 = *(const float4*)&Bs[kk][tx * 8 + 4];
            float a[8] = {a0.x,a0.y,a0.z,a0.w,a1.x,a1.y,a1.z,a1.w};
            float b[8] = {b0.x,b0.y,b0.z,b0.w,b1.x,b1.y,b1.z,b1.w};
#pragma unroll
            for (int i = 0; i < 8; i++)
#pragma unroll
                for (int j = 0; j < 8; j++)
                    acc[i][j] += a[i] * b[j];
        }
    }

    float* Cb = C + (size_t)(bm + ty * 8) * N + bn + tx * 8;
#pragma unroll
    for (int i = 0; i < 8; i++) {
        float4 c0 = make_float4(acc[i][0], acc[i][1], acc[i][2], acc[i][3]);
        float4 c1 = make_float4(acc[i][4], acc[i][5], acc[i][6], acc[i][7]);
        *(float4*)(Cb + (size_t)i * N)     = c0;
        *(float4*)(Cb + (size_t)i * N + 4) = c1;
    }
}

// ---------------------------------------------------------------------------
// counts[b][s] = inclusive prefix sum over s of (mask[b,s]==0)
// one block per batch, 256 threads x 8 elems
// ---------------------------------------------------------------------------
__global__ __launch_bounds__(256) void counts_kernel(
    const float* __restrict__ mask, float* __restrict__ cnt)
{
    __shared__ float part[256];
    const int b = blockIdx.x;
    const int t = threadIdx.x;
    const int base = b * Sc;

    float local[8];
    float sum = 0.f;
#pragma unroll
    for (int j = 0; j < 8; j++) {
        int s = t * 8 + j;
        float kp = (mask[base + s] == 0.f) ? 1.f : 0.f;
        sum += kp;
        local[j] = sum;            // inclusive within chunk
    }
    part[t] = sum;
    __syncthreads();
    if (t == 0) {
        float run = 0.f;
        for (int i = 0; i < 256; i++) { float tmp = part[i]; part[i] = run; run += tmp; }
    }
    __syncthreads();
    float off = part[t];
#pragma unroll
    for (int j = 0; j < 8; j++)
        cnt[base + t * 8 + j] = off + local[j];
}

// ---------------------------------------------------------------------------
// RoPE (GPT-J interleaved, first 64 dims) + L2 normalize over head + keep mask
// one block per (b,s,h) row, 128 threads (one per dim)
// ---------------------------------------------------------------------------
__global__ __launch_bounds__(128) void rope_norm_kernel(
    float* __restrict__ X, const float* __restrict__ mask,
    const int* __restrict__ pos)
{
    const int bsh = blockIdx.x;
    const int h  = bsh & (Hc - 1);
    const int bs = bsh >> 4;             // b*S + s

    float* row = X + (size_t)bs * Dc + h * HDc;
    const int d = threadIdx.x;

    __shared__ float sx[HDc];
    __shared__ float red[4];

    float x = row[d];
    sx[d] = x;
    __syncthreads();

    float y;
    if (d < ROTc) {
        int i = d >> 1;
        float inv = powf(10000.f, -(float)(2 * i) / (float)ROTc);
        float ang = (float)pos[bs] * inv;
        float sn, cs;
        sincosf(ang, &sn, &cs);
        float other = (d & 1) ? sx[d - 1] : sx[d + 1];
        y = (d & 1) ? (x * cs + other * sn) : (x * cs - other * sn);
    } else {
        y = x;
    }

    float ss = y * y;
#pragma unroll
    for (int off = 16; off; off >>= 1)
        ss += __shfl_xor_sync(0xffffffffu, ss, off);
    if ((d & 31) == 0) red[d >> 5] = ss;
    __syncthreads();
    float tot = red[0] + red[1] + red[2] + red[3];
    float nrm = sqrtf(tot);

    float keep = (mask[bs] == 0.f) ? 1.f : 0.f;
    row[d] = y / fmaxf(nrm, 1e-12f) * keep;
}

// ---------------------------------------------------------------------------
// V scaling: v[b,h,s,:] *= keep[b,s] / max(cnt[b,s]^sigmoid(nc[h]), 1)
// ---------------------------------------------------------------------------
__global__ __launch_bounds__(128) void vscale_kernel(
    float* __restrict__ V, const float* __restrict__ mask,
    const float* __restrict__ cnt, const float* __restrict__ nc)
{
    const int bsh = blockIdx.x;
    const int h  = bsh & (Hc - 1);
    const int bs = bsh >> 4;

    float keep = (mask[bs] == 0.f) ? 1.f : 0.f;
    float expo = 1.f / (1.f + expf(-nc[h]));
    float c = cnt[bs];
    float scale = keep / fmaxf(powf(c, expo), 1.f);
    V[(size_t)bs * Dc + h * HDc + threadIdx.x] *= scale;
}

// ---------------------------------------------------------------------------
// Causal attention (no softmax): O[q,:] = sum_{k<=q} (Qn[q]·Kn[k]) * V[k,:]
// grid: (S/64 qtiles, B*H), 256 threads. 64q x 64k tiles, HD=128.
// Rows padded to 129 floats in smem for conflict-free strided access.
// ---------------------------------------------------------------------------
#define AQ 64
#define AK 64
#define QPAD 129
#define PPAD 65
#define ATTN_SMEM ((3 * AQ * QPAD + AQ * PPAD) * (int)sizeof(float))

__global__ __launch_bounds__(256) void attn_kernel(
    const float* __restrict__ Q, const float* __restrict__ Kb,
    const float* __restrict__ V, float* __restrict__ O)
{
    extern __shared__ float sm[];
    float* Qs = sm;
    float* Ks = Qs + AQ * QPAD;
    float* Vs = Ks + AK * QPAD;
    float* Ps = Vs + AK * QPAD;

    const int bh = blockIdx.y;
    const int b = bh >> 4;
    const int h = bh & (Hc - 1);
    const int qt = blockIdx.x;

    const int tid = threadIdx.x;
    const int tx = tid & 15;
    const int ty = tid >> 4;

    const float* Qg = Q + ((size_t)(b * Sc + qt * AQ)) * Dc + h * HDc;

    // stage Q tile (64 rows x 128 floats)
    for (int idx = tid; idx < AQ * 32; idx += 256) {
        int r = idx >> 5, c4 = (idx & 31) * 4;
        float4 v = *(const float4*)(Qg + (size_t)r * Dc + c4);
        float* dst = Qs + r * QPAD + c4;
        dst[0] = v.x; dst[1] = v.y; dst[2] = v.z; dst[3] = v.w;
    }

    float o[4][8];
#pragma unroll
    for (int i = 0; i < 4; i++)
#pragma unroll
        for (int j = 0; j < 8; j++) o[i][j] = 0.f;

    for (int jt = 0; jt <= qt; jt++) {
        const float* Kg = Kb + ((size_t)(b * Sc + jt * AK)) * Dc + h * HDc;
        const float* Vg = V  + ((size_t)(b * Sc + jt * AK)) * Dc + h * HDc;

        __syncthreads();   // previous iter done with Ks/Vs; Q stores visible
        for (int idx = tid; idx < AK * 32; idx += 256) {
            int r = idx >> 5, c4 = (idx & 31) * 4;
            float4 kv = *(const float4*)(Kg + (size_t)r * Dc + c4);
            float4 vv = *(const float4*)(Vg + (size_t)r * Dc + c4);
            float* kd = Ks + r * QPAD + c4;
            kd[0] = kv.x; kd[1] = kv.y; kd[2] = kv.z; kd[3] = kv.w;
            float* vd = Vs + r * QPAD + c4;
            vd[0] = vv.x; vd[1] = vv.y; vd[2] = vv.z; vd[3] = vv.w;
        }
        __syncthreads();

        // P[q,k] = Qn[q] . Kn[k]  (thread owns q = 16i+ty, k = 16j+tx)
        float p[4][4];
#pragma unroll
        for (int i = 0; i < 4; i++)
#pragma unroll
            for (int j = 0; j < 4; j++) p[i][j] = 0.f;

#pragma unroll 4
        for (int d = 0; d < HDc; d++) {
            float a[4], bb[4];
#pragma unroll
            for (int i = 0; i < 4; i++) a[i]  = Qs[(16 * i + ty) * QPAD + d];
#pragma unroll
            for (int j = 0; j < 4; j++) bb[j] = Ks[(16 * j + tx) * QPAD + d];
#pragma unroll
            for (int i = 0; i < 4; i++)
#pragma unroll
                for (int j = 0; j < 4; j++)
                    p[i][j] += a[i] * bb[j];
        }

        const bool diag = (jt == qt);
#pragma unroll
        for (int i = 0; i < 4; i++) {
            int ql = 16 * i + ty;
#pragma unroll
            for (int j = 0; j < 4; j++) {
                int kl = 16 * j + tx;
                float val = p[i][j];
                if (diag && kl > ql) val = 0.f;
                Ps[ql * PPAD + kl] = val;
            }
        }
        __syncthreads();

        // O += P * V   (thread owns q = 16i+ty, d = 16j+tx)
#pragma unroll 2
        for (int kk = 0; kk < AK; kk++) {
            float pv[4], vv[8];
#pragma unroll
            for (int i = 0; i < 4; i++) pv[i] = Ps[(16 * i + ty) * PPAD + kk];
#pragma unroll
            for (int j = 0; j < 8; j++) vv[j] = Vs[kk * QPAD + 16 * j + tx];
#pragma unroll
            for (int i = 0; i < 4; i++)
#pragma unroll
                for (int j = 0; j < 8; j++)
                    o[i][j] += pv[i] * vv[j];
        }
    }

    // write O in (b, s, h*HD + d) layout so the Wo GEMM can consume directly
    float* Og = O + ((size_t)(b * Sc + qt * AQ)) * Dc + h * HDc;
#pragma unroll
    for (int i = 0; i < 4; i++)
#pragma unroll
        for (int j = 0; j < 8; j++)
            Og[(size_t)(16 * i + ty) * Dc + 16 * j + tx] = o[i][j];
}

// ---------------------------------------------------------------------------
// launch
// ---------------------------------------------------------------------------
extern "C" void kernel_launch(void* const* d_in, const int* in_sizes, int n_in,
                              void* d_out, int out_size)
{
    const float* hs   = (const float*)d_in[0];
    const float* mask = (const float*)d_in[1];
    const int*   pos  = (const int*)  d_in[2];
    const float* Wq   = (const float*)d_in[3];
    const float* Wk   = (const float*)d_in[4];
    const float* Wv   = (const float*)d_in[5];
    const float* Wo   = (const float*)d_in[6];
    const float* nc   = (const float*)d_in[7];
    float* out = (float*)d_out;

    float *q, *k, *v, *ab, *cnt;
    cudaGetSymbolAddress((void**)&q,   g_q);
    cudaGetSymbolAddress((void**)&k,   g_k);
    cudaGetSymbolAddress((void**)&v,   g_v);
    cudaGetSymbolAddress((void**)&ab,  g_ab);
    cudaGetSymbolAddress((void**)&cnt, g_cnt);

    dim3 gemmGrid(Dc / GBN, Mc / GBM);   // (16, 32)

    counts_kernel<<<Bc, 256>>>(mask, cnt);

    gemm_nt<<<gemmGrid, 256>>>(hs, Wq, q, Mc, Dc, Dc);
    gemm_nt<<<gemmGrid, 256>>>(hs, Wk, k, Mc, Dc, Dc);
    gemm_nt<<<gemmGrid, 256>>>(hs, Wv, v, Mc, Dc, Dc);

    const int nrows = Bc * Sc * Hc;      // 65536
    rope_norm_kernel<<<nrows, 128>>>(q, mask, pos);
    rope_norm_kernel<<<nrows, 128>>>(k, mask, pos);
    vscale_kernel<<<nrows, 128>>>(v, mask, cnt, nc);

    cudaFuncSetAttribute(attn_kernel,
                         cudaFuncAttributeMaxDynamicSharedMemorySize, ATTN_SMEM);
    dim3 attnGrid(Sc / AQ, Bc * Hc);     // (32, 32)
    attn_kernel<<<attnGrid, 256, ATTN_SMEM>>>(q, k, v, ab);

    gemm_nt<<<gemmGrid, 256>>>(ab, Wo, out, Mc, Dc, Dc);
}

// round 2
// speedup vs baseline: 1.5372x; 1.5372x over previous
#include <cuda_runtime.h>
#include <math.h>
#include <stdint.h>

// Problem constants
#define Bc   2
#define Sc   2048
#define Dc   2048
#define Hc   16
#define HDc  128
#define ROTc 64
#define Mc   (Bc*Sc)   // 4096 rows in all projections

// ---------------------------------------------------------------------------
// Scratch (no cudaMalloc allowed)
// ---------------------------------------------------------------------------
__device__ float g_q [(size_t)Bc*Sc*Dc];
__device__ float g_k [(size_t)Bc*Sc*Dc];
__device__ float g_v [(size_t)Bc*Sc*Dc];
__device__ float g_ab[(size_t)Bc*Sc*Dc];
__device__ float g_cnt[Bc*Sc];

// ---------------------------------------------------------------------------
// Tensor-core tf32 GEMM: C[M,N] = A[M,K] * W[N,K]^T  (row-major, NT form)
// 128x128 block, BK=16, 4 warps (64x64 warp tile), double-buffered swizzled
// smem, mma.sync.m16n8k8 tf32.
// ---------------------------------------------------------------------------
#define GBM 128
#define GBN 128
#define GBK 16

__device__ __forceinline__ uint32_t f2tf32(float x) {
    uint32_t u;
    asm("cvt.rna.tf32.f32 %0, %1;" : "=r"(u) : "f"(x));
    return u;
}

__device__ __forceinline__ void mma_tf32(float c[4], const uint32_t a[4],
                                         const uint32_t b[2]) {
    asm volatile(
        "mma.sync.aligned.m16n8k8.row.col.f32.tf32.tf32.f32 "
        "{%0,%1,%2,%3}, {%4,%5,%6,%7}, {%8,%9}, {%0,%1,%2,%3};"
        : "+f"(c[0]), "+f"(c[1]), "+f"(c[2]), "+f"(c[3])
        : "r"(a[0]), "r"(a[1]), "r"(a[2]), "r"(a[3]),
          "r"(b[0]), "r"(b[1]));
}

__global__ __launch_bounds__(128, 2) void gemm_tc(
    const float* __restrict__ A, const float* __restrict__ W,
    float* __restrict__ C, int M, int N, int K)
{
    __shared__ uint32_t As[2][GBM][GBK];
    __shared__ uint32_t Bs[2][GBN][GBK];

    const int tid  = threadIdx.x;
    const int warp = tid >> 5, lane = tid & 31;
    const int gid  = lane >> 2, tig = lane & 3;
    const int wm   = (warp >> 1) * 64, wn = (warp & 1) * 64;
    const int bm   = blockIdx.y * GBM,  bn = blockIdx.x * GBN;

    const float* Ag = A + (size_t)(bm + tid) * K;
    const float* Wg = W + (size_t)(bn + tid) * K;

    float acc[4][8][4];
#pragma unroll
    for (int i = 0; i < 4; i++)
#pragma unroll
        for (int j = 0; j < 8; j++)
#pragma unroll
            for (int l = 0; l < 4; l++) acc[i][j][l] = 0.f;

    const int swz = (tid >> 1) & 3;
    float4 pa[4], pb[4];

    // prologue: load + stage tile 0
#pragma unroll
    for (int i = 0; i < 4; i++) {
        pa[i] = *(const float4*)(Ag + i * 4);
        pb[i] = *(const float4*)(Wg + i * 4);
    }
#pragma unroll
    for (int i = 0; i < 4; i++) {
        int cg = i ^ swz;
        uint4 sa, sb;
        sa.x = f2tf32(pa[i].x); sa.y = f2tf32(pa[i].y);
        sa.z = f2tf32(pa[i].z); sa.w = f2tf32(pa[i].w);
        sb.x = f2tf32(pb[i].x); sb.y = f2tf32(pb[i].y);
        sb.z = f2tf32(pb[i].z); sb.w = f2tf32(pb[i].w);
        *(uint4*)&As[0][tid][cg * 4] = sa;
        *(uint4*)&Bs[0][tid][cg * 4] = sb;
    }
    __syncthreads();

    const int NT = K / GBK;
    for (int kt = 0; kt < NT; kt++) {
        const int buf = kt & 1;
        const bool more = (kt + 1 < NT);

        if (more) {
#pragma unroll
            for (int i = 0; i < 4; i++) {
                pa[i] = *(const float4*)(Ag + (kt + 1) * GBK + i * 4);
                pb[i] = *(const float4*)(Wg + (kt + 1) * GBK + i * 4);
            }
        }

#pragma unroll
        for (int ks = 0; ks < 2; ks++) {
            const int g0 = ks * 2, g1 = g0 + 1;
            uint32_t af[4][4], bf[8][2];
#pragma unroll
            for (int mt = 0; mt < 4; mt++) {
                int r0 = wm + mt * 16 + gid, r1 = r0 + 8;
                af[mt][0] = As[buf][r0][((g0 ^ ((r0 >> 1) & 3)) << 2) | tig];
                af[mt][1] = As[buf][r1][((g0 ^ ((r1 >> 1) & 3)) << 2) | tig];
                af[mt][2] = As[buf][r0][((g1 ^ ((r0 >> 1) & 3)) << 2) | tig];
                af[mt][3] = As[buf][r1][((g1 ^ ((r1 >> 1) & 3)) << 2) | tig];
            }
#pragma unroll
            for (int nt = 0; nt < 8; nt++) {
                int rn = wn + nt * 8 + gid;
                bf[nt][0] = Bs[buf][rn][((g0 ^ ((rn >> 1) & 3)) << 2) | tig];
                bf[nt][1] = Bs[buf][rn][((g1 ^ ((rn >> 1) & 3)) << 2) | tig];
            }
#pragma unroll
            for (int mt = 0; mt < 4; mt++)
#pragma unroll
                for (int nt = 0; nt < 8; nt++)
                    mma_tf32(acc[mt][nt], af[mt], bf[nt]);
        }

        if (more) {
#pragma unroll
            for (int i = 0; i < 4; i++) {
                int cg = i ^ swz;
                uint4 sa, sb;
                sa.x = f2tf32(pa[i].x); sa.y = f2tf32(pa[i].y);
                sa.z = f2tf32(pa[i].z); sa.w = f2tf32(pa[i].w);
                sb.x = f2tf32(pb[i].x); sb.y = f2tf32(pb[i].y);
                sb.z = f2tf32(pb[i].z); sb.w = f2tf32(pb[i].w);
                *(uint4*)&As[buf ^ 1][tid][cg * 4] = sa;
                *(uint4*)&Bs[buf ^ 1][tid][cg * 4] = sb;
            }
        }
        __syncthreads();
    }

    // epilogue
#pragma unroll
    for (int mt = 0; mt < 4; mt++) {
        int r0 = bm + wm + mt * 16 + gid;
#pragma unroll
        for (int nt = 0; nt < 8; nt++) {
            int c0 = bn + wn + nt * 8 + tig * 2;
            float2 v0 = make_float2(acc[mt][nt][0], acc[mt][nt][1]);
            float2 v1 = make_float2(acc[mt][nt][2], acc[mt][nt][3]);
            *(float2*)&C[(size_t)r0 * N + c0]       = v0;
            *(float2*)&C[(size_t)(r0 + 8) * N + c0] = v1;
        }
    }
}

// ---------------------------------------------------------------------------
// counts[b][s] = inclusive prefix sum over s of (mask[b,s]==0)
// ---------------------------------------------------------------------------
__global__ __launch_bounds__(256) void counts_kernel(
    const float* __restrict__ mask, float* __restrict__ cnt)
{
    __shared__ float part[256];
    const int b = blockIdx.x;
    const int t = threadIdx.x;
    const int base = b * Sc;

    float local[8];
    float sum = 0.f;
#pragma unroll
    for (int j = 0; j < 8; j++) {
        int s = t * 8 + j;
        float kp = (mask[base + s] == 0.f) ? 1.f : 0.f;
        sum += kp;
        local[j] = sum;
    }
    part[t] = sum;
    __syncthreads();
    if (t == 0) {
        float run = 0.f;
        for (int i = 0; i < 256; i++) { float tmp = part[i]; part[i] = run; run += tmp; }
    }
    __syncthreads();
    float off = part[t];
#pragma unroll
    for (int j = 0; j < 8; j++)
        cnt[base + t * 8 + j] = off + local[j];
}

// ---------------------------------------------------------------------------
// RoPE + L2 normalize + keep mask
// ---------------------------------------------------------------------------
__global__ __launch_bounds__(128) void rope_norm_kernel(
    float* __restrict__ X, const float* __restrict__ mask,
    const int* __restrict__ pos)
{
    const int bsh = blockIdx.x;
    const int h  = bsh & (Hc - 1);
    const int bs = bsh >> 4;

    float* row = X + (size_t)bs * Dc + h * HDc;
    const int d = threadIdx.x;

    __shared__ float sx[HDc];
    __shared__ float red[4];

    float x = row[d];
    sx[d] = x;
    __syncthreads();

    float y;
    if (d < ROTc) {
        int i = d >> 1;
        float inv = powf(10000.f, -(float)(2 * i) / (float)ROTc);
        float ang = (float)pos[bs] * inv;
        float sn, cs;
        sincosf(ang, &sn, &cs);
        float other = (d & 1) ? sx[d - 1] : sx[d + 1];
        y = (d & 1) ? (x * cs + other * sn) : (x * cs - other * sn);
    } else {
        y = x;
    }

    float ss = y * y;
#pragma unroll
    for (int off = 16; off; off >>= 1)
        ss += __shfl_xor_sync(0xffffffffu, ss, off);
    if ((d & 31) == 0) red[d >> 5] = ss;
    __syncthreads();
    float tot = red[0] + red[1] + red[2] + red[3];
    float nrm = sqrtf(tot);

    float keep = (mask[bs] == 0.f) ? 1.f : 0.f;
    row[d] = y / fmaxf(nrm, 1e-12f) * keep;
}

// ---------------------------------------------------------------------------
// V scaling
// ---------------------------------------------------------------------------
__global__ __launch_bounds__(128) void vscale_kernel(
    float* __restrict__ V, const float* __restrict__ mask,
    const float* __restrict__ cnt, const float* __restrict__ nc)
{
    const int bsh = blockIdx.x;
    const int h  = bsh & (Hc - 1);
    const int bs = bsh >> 4;

    float keep = (mask[bs] == 0.f) ? 1.f : 0.f;
    float expo = 1.f / (1.f + expf(-nc[h]));
    float c = cnt[bs];
    float scale = keep / fmaxf(powf(c, expo), 1.f);
    V[(size_t)bs * Dc + h * HDc + threadIdx.x] *= scale;
}

// ---------------------------------------------------------------------------
// Causal attention (no softmax), SIMT fp32 (unchanged from R1)
// ---------------------------------------------------------------------------
#define AQ 64
#define AK 64
#define QPAD 129
#define PPAD 65
#define ATTN_SMEM ((3 * AQ * QPAD + AQ * PPAD) * (int)sizeof(float))

__global__ __launch_bounds__(256) void attn_kernel(
    const float* __restrict__ Q, const float* __restrict__ Kb,
    const float* __restrict__ V, float* __restrict__ O)
{
    extern __shared__ float sm[];
    float* Qs = sm;
    float* Ks = Qs + AQ * QPAD;
    float* Vs = Ks + AK * QPAD;
    float* Ps = Vs + AK * QPAD;

    const int bh = blockIdx.y;
    const int b = bh >> 4;
    const int h = bh & (Hc - 1);
    const int qt = blockIdx.x;

    const int tid = threadIdx.x;
    const int tx = tid & 15;
    const int ty = tid >> 4;

    const float* Qg = Q + ((size_t)(b * Sc + qt * AQ)) * Dc + h * HDc;

    for (int idx = tid; idx < AQ * 32; idx += 256) {
        int r = idx >> 5, c4 = (idx & 31) * 4;
        float4 v = *(const float4*)(Qg + (size_t)r * Dc + c4);
        float* dst = Qs + r * QPAD + c4;
        dst[0] = v.x; dst[1] = v.y; dst[2] = v.z; dst[3] = v.w;
    }

    float o[4][8];
#pragma unroll
    for (int i = 0; i < 4; i++)
#pragma unroll
        for (int j = 0; j < 8; j++) o[i][j] = 0.f;

    for (int jt = 0; jt <= qt; jt++) {
        const float* Kg = Kb + ((size_t)(b * Sc + jt * AK)) * Dc + h * HDc;
        const float* Vg = V  + ((size_t)(b * Sc + jt * AK)) * Dc + h * HDc;

        __syncthreads();
        for (int idx = tid; idx < AK * 32; idx += 256) {
            int r = idx >> 5, c4 = (idx & 31) * 4;
            float4 kv = *(const float4*)(Kg + (size_t)r * Dc + c4);
            float4 vv = *(const float4*)(Vg + (size_t)r * Dc + c4);
            float* kd = Ks + r * QPAD + c4;
            kd[0] = kv.x; kd[1] = kv.y; kd[2] = kv.z; kd[3] = kv.w;
            float* vd = Vs + r * QPAD + c4;
            vd[0] = vv.x; vd[1] = vv.y; vd[2] = vv.z; vd[3] = vv.w;
        }
        __syncthreads();

        float p[4][4];
#pragma unroll
        for (int i = 0; i < 4; i++)
#pragma unroll
            for (int j = 0; j < 4; j++) p[i][j] = 0.f;

#pragma unroll 4
        for (int d = 0; d < HDc; d++) {
            float a[4], bb[4];
#pragma unroll
            for (int i = 0; i < 4; i++) a[i]  = Qs[(16 * i + ty) * QPAD + d];
#pragma unroll
            for (int j = 0; j < 4; j++) bb[j] = Ks[(16 * j + tx) * QPAD + d];
#pragma unroll
            for (int i = 0; i < 4; i++)
#pragma unroll
                for (int j = 0; j < 4; j++)
                    p[i][j] += a[i] * bb[j];
        }

        const bool diag = (jt == qt);
#pragma unroll
        for (int i = 0; i < 4; i++) {
            int ql = 16 * i + ty;
#pragma unroll
            for (int j = 0; j < 4; j++) {
                int kl = 16 * j + tx;
                float val = p[i][j];
                if (diag && kl > ql) val = 0.f;
                Ps[ql * PPAD + kl] = val;
            }
        }
        __syncthreads();

#pragma unroll 2
        for (int kk = 0; kk < AK; kk++) {
            float pv[4], vv[8];
#pragma unroll
            for (int i = 0; i < 4; i++) pv[i] = Ps[(16 * i + ty) * PPAD + kk];
#pragma unroll
            for (int j = 0; j < 8; j++) vv[j] = Vs[kk * QPAD + 16 * j + tx];
#pragma unroll
            for (int i = 0; i < 4; i++)
#pragma unroll
                for (int j = 0; j < 8; j++)
                    o[i][j] += pv[i] * vv[j];
        }
    }

    float* Og = O + ((size_t)(b * Sc + qt * AQ)) * Dc + h * HDc;
#pragma unroll
    for (int i = 0; i < 4; i++)
#pragma unroll
        for (int j = 0; j < 8; j++)
            Og[(size_t)(16 * i + ty) * Dc + 16 * j + tx] = o[i][j];
}

// ---------------------------------------------------------------------------
// launch
// ---------------------------------------------------------------------------
extern "C" void kernel_launch(void* const* d_in, const int* in_sizes, int n_in,
                              void* d_out, int out_size)
{
    const float* hs   = (const float*)d_in[0];
    const float* mask = (const float*)d_in[1];
    const int*   pos  = (const int*)  d_in[2];
    const float* Wq   = (const float*)d_in[3];
    const float* Wk   = (const float*)d_in[4];
    const float* Wv   = (const float*)d_in[5];
    const float* Wo   = (const float*)d_in[6];
    const float* nc   = (const float*)d_in[7];
    float* out = (float*)d_out;

    float *q, *k, *v, *ab, *cnt;
    cudaGetSymbolAddress((void**)&q,   g_q);
    cudaGetSymbolAddress((void**)&k,   g_k);
    cudaGetSymbolAddress((void**)&v,   g_v);
    cudaGetSymbolAddress((void**)&ab,  g_ab);
    cudaGetSymbolAddress((void**)&cnt, g_cnt);

    dim3 gemmGrid(Dc / GBN, Mc / GBM);   // (16, 32)

    counts_kernel<<<Bc, 256>>>(mask, cnt);

    gemm_tc<<<gemmGrid, 128>>>(hs, Wq, q, Mc, Dc, Dc);
    gemm_tc<<<gemmGrid, 128>>>(hs, Wk, k, Mc, Dc, Dc);
    gemm_tc<<<gemmGrid, 128>>>(hs, Wv, v, Mc, Dc, Dc);

    const int nrows = Bc * Sc * Hc;      // 65536
    rope_norm_kernel<<<nrows, 128>>>(q, mask, pos);
    rope_norm_kernel<<<nrows, 128>>>(k, mask, pos);
    vscale_kernel<<<nrows, 128>>>(v, mask, cnt, nc);

    cudaFuncSetAttribute(attn_kernel,
                         cudaFuncAttributeMaxDynamicSharedMemorySize, ATTN_SMEM);
    dim3 attnGrid(Sc / AQ, Bc * Hc);     // (32, 32)
    attn_kernel<<<attnGrid, 256, ATTN_SMEM>>>(q, k, v, ab);

    gemm_tc<<<gemmGrid, 128>>>(ab, Wo, out, Mc, Dc, Dc);
}

// round 4
// speedup vs baseline: 2.4709x; 1.6074x over previous
#include <cuda_runtime.h>
#include <math.h>
#include <stdint.h>

// Problem constants
#define Bc   2
#define Sc   2048
#define Dc   2048
#define Hc   16
#define HDc  128
#define ROTc 64
#define Mc   (Bc*Sc)   // 4096 rows in all projections

// ---------------------------------------------------------------------------
// Scratch
// ---------------------------------------------------------------------------
__device__ float g_q [(size_t)Bc*Sc*Dc];
__device__ float g_k [(size_t)Bc*Sc*Dc];
__device__ float g_v [(size_t)Bc*Sc*Dc];
__device__ float g_ab[(size_t)Bc*Sc*Dc];
__device__ float g_cnt[Bc*Sc];

// ---------------------------------------------------------------------------
// mma.sync tf32 helpers (sm_90-era PTX, legal at compute_100)
// ---------------------------------------------------------------------------
__device__ __forceinline__ uint32_t f2tf32(float x) {
    uint32_t u;
    asm("cvt.rna.tf32.f32 %0, %1;" : "=r"(u) : "f"(x));
    return u;
}

__device__ __forceinline__ void mma_tf32(float c[4], const uint32_t a[4],
                                         const uint32_t b[2]) {
    asm volatile(
        "mma.sync.aligned.m16n8k8.row.col.f32.tf32.tf32.f32 "
        "{%0,%1,%2,%3}, {%4,%5,%6,%7}, {%8,%9}, {%0,%1,%2,%3};"
        : "+f"(c[0]), "+f"(c[1]), "+f"(c[2]), "+f"(c[3])
        : "r"(a[0]), "r"(a[1]), "r"(a[2]), "r"(a[3]),
          "r"(b[0]), "r"(b[1]));
}

// ---------------------------------------------------------------------------
// Tensor-core tf32 GEMM: C[M,N] = A[M,K]*W[N,K]^T.  128x128 block, BK=16,
// 256 threads / 8 warps (warp tile 64x32), double-buffered swizzled smem.
// ---------------------------------------------------------------------------
#define GBM 128
#define GBN 128
#define GBK 16

__global__ __launch_bounds__(256, 2) void gemm_tc(
    const float* __restrict__ A, const float* __restrict__ W,
    float* __restrict__ C, int M, int N, int K)
{
    __shared__ uint32_t As[2][GBM][GBK];
    __shared__ uint32_t Bs[2][GBN][GBK];

    const int tid  = threadIdx.x;
    const int warp = tid >> 5, lane = tid & 31;
    const int gid  = lane >> 2, tig = lane & 3;
    const int wm   = (warp >> 2) * 64, wn = (warp & 3) * 32;
    const int bm   = blockIdx.y * GBM,  bn = blockIdx.x * GBN;

    const int lr  = tid >> 1;            // row 0..127
    const int lg0 = (tid & 1) * 2;       // first float4 group (of 4)

    const float* Ag = A + (size_t)(bm + lr) * K;
    const float* Wg = W + (size_t)(bn + lr) * K;
    const int swz = (lr >> 1) & 3;

    float acc[4][4][4];
#pragma unroll
    for (int i = 0; i < 4; i++)
#pragma unroll
        for (int j = 0; j < 4; j++)
#pragma unroll
            for (int l = 0; l < 4; l++) acc[i][j][l] = 0.f;

    float4 pa[2], pb[2];

    // prologue: load + stage tile 0
#pragma unroll
    for (int i = 0; i < 2; i++) {
        pa[i] = *(const float4*)(Ag + (lg0 + i) * 4);
        pb[i] = *(const float4*)(Wg + (lg0 + i) * 4);
    }
#pragma unroll
    for (int i = 0; i < 2; i++) {
        int cg = (lg0 + i) ^ swz;
        uint4 sa, sb;
        sa.x = f2tf32(pa[i].x); sa.y = f2tf32(pa[i].y);
        sa.z = f2tf32(pa[i].z); sa.w = f2tf32(pa[i].w);
        sb.x = f2tf32(pb[i].x); sb.y = f2tf32(pb[i].y);
        sb.z = f2tf32(pb[i].z); sb.w = f2tf32(pb[i].w);
        *(uint4*)&As[0][lr][cg * 4] = sa;
        *(uint4*)&Bs[0][lr][cg * 4] = sb;
    }
    __syncthreads();

    const int NT = K / GBK;
    for (int kt = 0; kt < NT; kt++) {
        const int buf = kt & 1;
        const bool more = (kt + 1 < NT);

        if (more) {
#pragma unroll
            for (int i = 0; i < 2; i++) {
                pa[i] = *(const float4*)(Ag + (kt + 1) * GBK + (lg0 + i) * 4);
                pb[i] = *(const float4*)(Wg + (kt + 1) * GBK + (lg0 + i) * 4);
            }
        }

#pragma unroll
        for (int ks = 0; ks < 2; ks++) {
            const int g0 = ks * 2, g1 = g0 + 1;
            uint32_t af[4][4], bf[4][2];
#pragma unroll
            for (int mt = 0; mt < 4; mt++) {
                int r0 = wm + mt * 16 + gid, r1 = r0 + 8;
                af[mt][0] = As[buf][r0][((g0 ^ ((r0 >> 1) & 3)) << 2) | tig];
                af[mt][1] = As[buf][r1][((g0 ^ ((r1 >> 1) & 3)) << 2) | tig];
                af[mt][2] = As[buf][r0][((g1 ^ ((r0 >> 1) & 3)) << 2) | tig];
                af[mt][3] = As[buf][r1][((g1 ^ ((r1 >> 1) & 3)) << 2) | tig];
            }
#pragma unroll
            for (int nt = 0; nt < 4; nt++) {
                int rn = wn + nt * 8 + gid;
                bf[nt][0] = Bs[buf][rn][((g0 ^ ((rn >> 1) & 3)) << 2) | tig];
                bf[nt][1] = Bs[buf][rn][((g1 ^ ((rn >> 1) & 3)) << 2) | tig];
            }
#pragma unroll
            for (int mt = 0; mt < 4; mt++)
#pragma unroll
                for (int nt = 0; nt < 4; nt++)
                    mma_tf32(acc[mt][nt], af[mt], bf[nt]);
        }

        if (more) {
#pragma unroll
            for (int i = 0; i < 2; i++) {
                int cg = (lg0 + i) ^ swz;
                uint4 sa, sb;
                sa.x = f2tf32(pa[i].x); sa.y = f2tf32(pa[i].y);
                sa.z = f2tf32(pa[i].z); sa.w = f2tf32(pa[i].w);
                sb.x = f2tf32(pb[i].x); sb.y = f2tf32(pb[i].y);
                sb.z = f2tf32(pb[i].z); sb.w = f2tf32(pb[i].w);
                *(uint4*)&As[buf ^ 1][lr][cg * 4] = sa;
                *(uint4*)&Bs[buf ^ 1][lr][cg * 4] = sb;
            }
        }
        __syncthreads();
    }

    // epilogue
#pragma unroll
    for (int mt = 0; mt < 4; mt++) {
        int r0 = bm + wm + mt * 16 + gid;
#pragma unroll
        for (int nt = 0; nt < 4; nt++) {
            int c0 = bn + wn + nt * 8 + tig * 2;
            *(float2*)&C[(size_t)r0 * N + c0]       = make_float2(acc[mt][nt][0], acc[mt][nt][1]);
            *(float2*)&C[(size_t)(r0 + 8) * N + c0] = make_float2(acc[mt][nt][2], acc[mt][nt][3]);
        }
    }
}

// ---------------------------------------------------------------------------
// counts
// ---------------------------------------------------------------------------
__global__ __launch_bounds__(256) void counts_kernel(
    const float* __restrict__ mask, float* __restrict__ cnt)
{
    __shared__ float part[256];
    const int b = blockIdx.x;
    const int t = threadIdx.x;
    const int base = b * Sc;

    float local[8];
    float sum = 0.f;
#pragma unroll
    for (int j = 0; j < 8; j++) {
        int s = t * 8 + j;
        float kp = (mask[base + s] == 0.f) ? 1.f : 0.f;
        sum += kp;
        local[j] = sum;
    }
    part[t] = sum;
    __syncthreads();
    if (t == 0) {
        float run = 0.f;
        for (int i = 0; i < 256; i++) { float tmp = part[i]; part[i] = run; run += tmp; }
    }
    __syncthreads();
    float off = part[t];
#pragma unroll
    for (int j = 0; j < 8; j++)
        cnt[base + t * 8 + j] = off + local[j];
}

// ---------------------------------------------------------------------------
// RoPE + L2 normalize + keep mask
// ---------------------------------------------------------------------------
__global__ __launch_bounds__(128) void rope_norm_kernel(
    float* __restrict__ X, const float* __restrict__ mask,
    const int* __restrict__ pos)
{
    const int bsh = blockIdx.x;
    const int h  = bsh & (Hc - 1);
    const int bs = bsh >> 4;

    float* row = X + (size_t)bs * Dc + h * HDc;
    const int d = threadIdx.x;

    __shared__ float sx[HDc];
    __shared__ float red[4];

    float x = row[d];
    sx[d] = x;
    __syncthreads();

    float y;
    if (d < ROTc) {
        int i = d >> 1;
        float inv = powf(10000.f, -(float)(2 * i) / (float)ROTc);
        float ang = (float)pos[bs] * inv;
        float sn, cs;
        sincosf(ang, &sn, &cs);
        float other = (d & 1) ? sx[d - 1] : sx[d + 1];
        y = (d & 1) ? (x * cs + other * sn) : (x * cs - other * sn);
    } else {
        y = x;
    }

    float ss = y * y;
#pragma unroll
    for (int off = 16; off; off >>= 1)
        ss += __shfl_xor_sync(0xffffffffu, ss, off);
    if ((d & 31) == 0) red[d >> 5] = ss;
    __syncthreads();
    float tot = red[0] + red[1] + red[2] + red[3];
    float nrm = sqrtf(tot);

    float keep = (mask[bs] == 0.f) ? 1.f : 0.f;
    row[d] = y / fmaxf(nrm, 1e-12f) * keep;
}

// ---------------------------------------------------------------------------
// V scaling
// ---------------------------------------------------------------------------
__global__ __launch_bounds__(128) void vscale_kernel(
    float* __restrict__ V, const float* __restrict__ mask,
    const float* __restrict__ cnt, const float* __restrict__ nc)
{
    const int bsh = blockIdx.x;
    const int h  = bsh & (Hc - 1);
    const int bs = bsh >> 4;

    float keep = (mask[bs] == 0.f) ? 1.f : 0.f;
    float expo = 1.f / (1.f + expf(-nc[h]));
    float c = cnt[bs];
    float scale = keep / fmaxf(powf(c, expo), 1.f);
    V[(size_t)bs * Dc + h * HDc + threadIdx.x] *= scale;
}

// ---------------------------------------------------------------------------
// Tensor-core causal attention (no softmax), tf32 mma.sync.
// Block: 256 thr / 8 warps, 64 q-rows, k-tiles of 64, HD=128.
// Phase1 P=Q.K^T (warps: 4 q-slices x 2 k-halves); P masked -> smem tf32.
// Phase2 O+=P.V  (warps: 4 q-slices x 2 d-halves); V stored [k][d].
// Pitches: Q/K 132, P 68 (==4 mod 32), V 136 (==8 mod 32) -> conflict-free.
// ---------------------------------------------------------------------------
#define AQT 64
#define AKT 64
#define QP  132
#define VP  136
#define PP  68
#define QS_OFF 0
#define KS_OFF (AQT*QP)                 // 8448
#define VS_OFF (KS_OFF + AKT*QP)        // 16896
#define PS_OFF (VS_OFF + AKT*VP)        // 25600
#define ATTN_U32 (PS_OFF + AQT*PP)      // 29952
#define ATTN_SMEM (ATTN_U32 * 4)        // 119808 bytes

__global__ __launch_bounds__(256) void attn_tc_kernel(
    const float* __restrict__ Q, const float* __restrict__ Kb,
    const float* __restrict__ V, float* __restrict__ O)
{
    extern __shared__ uint32_t sm[];
    uint32_t* Qs = sm + QS_OFF;
    uint32_t* Ks = sm + KS_OFF;
    uint32_t* Vs = sm + VS_OFF;
    uint32_t* Ps = sm + PS_OFF;

    const int bh = blockIdx.y;
    const int b = bh >> 4;
    const int h = bh & (Hc - 1);
    const int qt = blockIdx.x;

    const int tid  = threadIdx.x;
    const int warp = tid >> 5, lane = tid & 31;
    const int gid  = lane >> 2, tig = lane & 3;
    const int wq   = (warp >> 1) * 16;        // q slice (both phases)
    const int wk1  = (warp & 1) * 32;         // phase1 k half
    const int wd2  = (warp & 1) * 64;         // phase2 d half

    const float* Qg = Q + ((size_t)(b * Sc + qt * AQT)) * Dc + h * HDc;

    // stage Q tile once (cvt to tf32)
    for (int idx = tid; idx < AQT * 32; idx += 256) {
        int r = idx >> 5, c4 = (idx & 31) * 4;
        float4 v = *(const float4*)(Qg + (size_t)r * Dc + c4);
        uint4 u = make_uint4(f2tf32(v.x), f2tf32(v.y), f2tf32(v.z), f2tf32(v.w));
        *(uint4*)&Qs[r * QP + c4] = u;
    }

    float oacc[8][4];
#pragma unroll
    for (int i = 0; i < 8; i++)
#pragma unroll
        for (int l = 0; l < 4; l++) oacc[i][l] = 0.f;

    for (int kt = 0; kt <= qt; kt++) {
        const float* Kg = Kb + ((size_t)(b * Sc + kt * AKT)) * Dc + h * HDc;
        const float* Vg = V  + ((size_t)(b * Sc + kt * AKT)) * Dc + h * HDc;

        __syncthreads();   // prev iter phase2 done; Q stores visible (iter 0)
        for (int idx = tid; idx < AKT * 32; idx += 256) {
            int r = idx >> 5, c4 = (idx & 31) * 4;
            float4 kv = *(const float4*)(Kg + (size_t)r * Dc + c4);
            float4 vv = *(const float4*)(Vg + (size_t)r * Dc + c4);
            *(uint4*)&Ks[r * QP + c4] =
                make_uint4(f2tf32(kv.x), f2tf32(kv.y), f2tf32(kv.z), f2tf32(kv.w));
            *(uint4*)&Vs[r * VP + c4] =
                make_uint4(f2tf32(vv.x), f2tf32(vv.y), f2tf32(vv.z), f2tf32(vv.w));
        }
        __syncthreads();

        // ---- phase 1: P[16q x 32k] per warp over d=128 ----
        float pacc[4][4];
#pragma unroll
        for (int i = 0; i < 4; i++)
#pragma unroll
            for (int l = 0; l < 4; l++) pacc[i][l] = 0.f;

#pragma unroll
        for (int ks = 0; ks < 16; ks++) {
            const int kb = ks * 8;
            uint32_t a[4];
            int r0 = wq + gid, r1 = r0 + 8;
            a[0] = Qs[r0 * QP + kb + tig];
            a[1] = Qs[r1 * QP + kb + tig];
            a[2] = Qs[r0 * QP + kb + 4 + tig];
            a[3] = Qs[r1 * QP + kb + 4 + tig];
#pragma unroll
            for (int nt = 0; nt < 4; nt++) {
                int rn = wk1 + nt * 8 + gid;
                uint32_t bfr[2];
                bfr[0] = Ks[rn * QP + kb + tig];
                bfr[1] = Ks[rn * QP + kb + 4 + tig];
                mma_tf32(pacc[nt], a, bfr);
            }
        }

        // mask (diag tile) + store P as tf32
        const bool diag = (kt == qt);
#pragma unroll
        for (int nt = 0; nt < 4; nt++) {
            int kl0 = wk1 + nt * 8 + tig * 2;
            int q0 = wq + gid, q1 = q0 + 8;
            float v00 = pacc[nt][0], v01 = pacc[nt][1];
            float v10 = pacc[nt][2], v11 = pacc[nt][3];
            if (diag) {
                if (kl0     > q0) v00 = 0.f;
                if (kl0 + 1 > q0) v01 = 0.f;
                if (kl0     > q1) v10 = 0.f;
                if (kl0 + 1 > q1) v11 = 0.f;
            }
            Ps[q0 * PP + kl0]     = f2tf32(v00);
            Ps[q0 * PP + kl0 + 1] = f2tf32(v01);
            Ps[q1 * PP + kl0]     = f2tf32(v10);
            Ps[q1 * PP + kl0 + 1] = f2tf32(v11);
        }
        __syncthreads();

        // ---- phase 2: O[16q x 64d] per warp over k=64 ----
#pragma unroll
        for (int ks = 0; ks < 8; ks++) {
            const int kb = ks * 8;
            uint32_t a[4];
            int r0 = wq + gid, r1 = r0 + 8;
            a[0] = Ps[r0 * PP + kb + tig];
            a[1] = Ps[r1 * PP + kb + tig];
            a[2] = Ps[r0 * PP + kb + 4 + tig];
            a[3] = Ps[r1 * PP + kb + 4 + tig];
#pragma unroll
            for (int nt = 0; nt < 8; nt++) {
                int dcol = wd2 + nt * 8 + gid;
                uint32_t bfr[2];
                bfr[0] = Vs[(kb + tig)     * VP + dcol];
                bfr[1] = Vs[(kb + 4 + tig) * VP + dcol];
                mma_tf32(oacc[nt], a, bfr);
            }
        }
    }

    // epilogue: write O (b, s, h*HD+d)
    float* Og = O + ((size_t)(b * Sc + qt * AQT)) * Dc + h * HDc;
    int q0 = wq + gid, q1 = q0 + 8;
#pragma unroll
    for (int nt = 0; nt < 8; nt++) {
        int d0 = wd2 + nt * 8 + tig * 2;
        *(float2*)&Og[(size_t)q0 * Dc + d0] = make_float2(oacc[nt][0], oacc[nt][1]);
        *(float2*)&Og[(size_t)q1 * Dc + d0] = make_float2(oacc[nt][2], oacc[nt][3]);
    }
}

// ---------------------------------------------------------------------------
// launch
// ---------------------------------------------------------------------------
extern "C" void kernel_launch(void* const* d_in, const int* in_sizes, int n_in,
                              void* d_out, int out_size)
{
    const float* hs   = (const float*)d_in[0];
    const float* mask = (const float*)d_in[1];
    const int*   pos  = (const int*)  d_in[2];
    const float* Wq   = (const float*)d_in[3];
    const float* Wk   = (const float*)d_in[4];
    const float* Wv   = (const float*)d_in[5];
    const float* Wo   = (const float*)d_in[6];
    const float* nc   = (const float*)d_in[7];
    float* out = (float*)d_out;

    float *q, *k, *v, *ab, *cnt;
    cudaGetSymbolAddress((void**)&q,   g_q);
    cudaGetSymbolAddress((void**)&k,   g_k);
    cudaGetSymbolAddress((void**)&v,   g_v);
    cudaGetSymbolAddress((void**)&ab,  g_ab);
    cudaGetSymbolAddress((void**)&cnt, g_cnt);

    cudaFuncSetAttribute(attn_tc_kernel,
                         cudaFuncAttributeMaxDynamicSharedMemorySize, ATTN_SMEM);

    dim3 gemmGrid(Dc / GBN, Mc / GBM);   // (16, 32)

    counts_kernel<<<Bc, 256>>>(mask, cnt);

    gemm_tc<<<gemmGrid, 256>>>(hs, Wq, q, Mc, Dc, Dc);
    gemm_tc<<<gemmGrid, 256>>>(hs, Wk, k, Mc, Dc, Dc);
    gemm_tc<<<gemmGrid, 256>>>(hs, Wv, v, Mc, Dc, Dc);

    const int nrows = Bc * Sc * Hc;      // 65536
    rope_norm_kernel<<<nrows, 128>>>(q, mask, pos);
    rope_norm_kernel<<<nrows, 128>>>(k, mask, pos);
    vscale_kernel<<<nrows, 128>>>(v, mask, cnt, nc);

    dim3 attnGrid(Sc / AQT, Bc * Hc);    // (32, 32)
    attn_tc_kernel<<<attnGrid, 256, ATTN_SMEM>>>(q, k, v, ab);

    gemm_tc<<<gemmGrid, 256>>>(ab, Wo, out, Mc, Dc, Dc);
}

// round 6
// speedup vs baseline: 3.5735x; 1.4462x over previous
#include <cuda_runtime.h>
#include <cuda_fp16.h>
#include <math.h>
#include <stdint.h>

// Problem constants
#define Bc   2
#define Sc   2048
#define Dc   2048
#define Hc   16
#define HDc  128
#define ROTc 64
#define Mc   (Bc*Sc)

// ---------------------------------------------------------------------------
// Scratch
// ---------------------------------------------------------------------------
__device__ float g_q [(size_t)Bc*Sc*Dc];
__device__ float g_k [(size_t)Bc*Sc*Dc];
__device__ float g_v [(size_t)Bc*Sc*Dc];
__device__ float g_ab[(size_t)Bc*Sc*Dc];
__device__ float g_cnt[Bc*Sc];

// ---------------------------------------------------------------------------
// helpers
// ---------------------------------------------------------------------------
__device__ __forceinline__ uint32_t smem_u32(const void* p) {
    uint32_t a;
    asm("{ .reg .u64 t; cvta.to.shared.u64 t, %1; cvt.u32.u64 %0, t; }"
        : "=r"(a) : "l"(p));
    return a;
}
__device__ __forceinline__ uint32_t f2tf32(float x) {
    uint32_t u;
    asm("cvt.rna.tf32.f32 %0, %1;" : "=r"(u) : "f"(x));
    return u;
}
__device__ __forceinline__ uint32_t pack_h2(float lo, float hi) {
    half2 h = __floats2half2_rn(lo, hi);
    return *(uint32_t*)&h;
}
__device__ __forceinline__ void sts128(uint32_t addr, uint4 v) {
    asm volatile("st.shared.v4.b32 [%0], {%1,%2,%3,%4};" ::
        "r"(addr), "r"(v.x), "r"(v.y), "r"(v.z), "r"(v.w));
}
__device__ __forceinline__ void ldm_x4(uint32_t r[4], uint32_t addr) {
    asm volatile("ldmatrix.sync.aligned.m8n8.x4.shared.b16 {%0,%1,%2,%3}, [%4];"
        : "=r"(r[0]), "=r"(r[1]), "=r"(r[2]), "=r"(r[3]) : "r"(addr));
}
__device__ __forceinline__ void mma_fp16(float c[4], const uint32_t a[4],
                                         const uint32_t b[2]) {
    asm volatile(
        "mma.sync.aligned.m16n8k16.row.col.f32.f16.f16.f32 "
        "{%0,%1,%2,%3}, {%4,%5,%6,%7}, {%8,%9}, {%0,%1,%2,%3};"
        : "+f"(c[0]), "+f"(c[1]), "+f"(c[2]), "+f"(c[3])
        : "r"(a[0]), "r"(a[1]), "r"(a[2]), "r"(a[3]),
          "r"(b[0]), "r"(b[1]));
}
__device__ __forceinline__ void mma_tf32(float c[4], const uint32_t a[4],
                                         const uint32_t b[2]) {
    asm volatile(
        "mma.sync.aligned.m16n8k8.row.col.f32.tf32.tf32.f32 "
        "{%0,%1,%2,%3}, {%4,%5,%6,%7}, {%8,%9}, {%0,%1,%2,%3};"
        : "+f"(c[0]), "+f"(c[1]), "+f"(c[2]), "+f"(c[3])
        : "r"(a[0]), "r"(a[1]), "r"(a[2]), "r"(a[3]),
          "r"(b[0]), "r"(b[1]));
}

// ---------------------------------------------------------------------------
// fp16 tensor-core GEMM: C[M,N] = A[M,K]*W[N,K]^T.
// 128x128 block, BK=32 halfs, 256 thr / 8 warps (warp tile 64x32),
// double-buffered swizzled smem, ldmatrix fragment loads, mma m16n8k16.
// Swizzle: 64B rows, 16B chunk c stored at phys = c ^ ((row>>1)&3).
// ---------------------------------------------------------------------------
#define GBM 128
#define GBN 128
#define GBK 32
#define GBUF 8192   // bytes per buffer (128 rows * 64B)

__global__ __launch_bounds__(256, 2) void gemm_fp16(
    const float* __restrict__ A, const float* __restrict__ W,
    float* __restrict__ C, int M, int N, int K)
{
    __shared__ half As[2][GBM][GBK];
    __shared__ half Bs[2][GBN][GBK];

    const int tid  = threadIdx.x;
    const int warp = tid >> 5, lane = tid & 31;
    const int gid  = lane >> 2, tig = lane & 3;
    const int wm   = (warp >> 2) * 64, wn = (warp & 3) * 32;
    const int bm   = blockIdx.y * GBM,  bn = blockIdx.x * GBN;

    const int lr = tid >> 1;        // row 0..127
    const int lh = tid & 1;         // 16-float half of the 32-float row

    const float* Ag = A + (size_t)(bm + lr) * K + lh * 16;
    const float* Wg = W + (size_t)(bn + lr) * K + lh * 16;

    const uint32_t As0 = smem_u32(As);
    const uint32_t Bs0 = smem_u32(Bs);

    // STS destinations (2 chunks per thread per array)
    uint32_t sta[2], stb[2];
#pragma unroll
    for (int cc = 0; cc < 2; cc++) {
        int chunk = lh * 2 + cc;
        int phys = chunk ^ ((lr >> 1) & 3);
        sta[cc] = As0 + lr * 64 + phys * 16;
        stb[cc] = Bs0 + lr * 64 + phys * 16;
    }

    // ldmatrix row bases
    uint32_t arow[4]; int axor[4];
    const int ahi = lane >> 4;               // chunk bit from lane
#pragma unroll
    for (int mt = 0; mt < 4; mt++) {
        int r = wm + 16 * mt + (lane & 7) + ((lane >> 3) & 1) * 8;
        arow[mt] = As0 + r * 64;
        axor[mt] = (r >> 1) & 3;
    }
    uint32_t brow[2]; int bxor[2];
    const int bhi = (lane >> 3) & 1;
#pragma unroll
    for (int n2 = 0; n2 < 2; n2++) {
        int r = wn + n2 * 16 + (lane & 7) + ((lane >> 4) & 1) * 8;
        brow[n2] = Bs0 + r * 64;
        bxor[n2] = (r >> 1) & 3;
    }

    float acc[4][4][4];
#pragma unroll
    for (int i = 0; i < 4; i++)
#pragma unroll
        for (int j = 0; j < 4; j++)
#pragma unroll
            for (int l = 0; l < 4; l++) acc[i][j][l] = 0.f;

    float4 pa[4], pb[4];

    // prologue: tile 0
#pragma unroll
    for (int j = 0; j < 4; j++) {
        pa[j] = *(const float4*)(Ag + j * 4);
        pb[j] = *(const float4*)(Wg + j * 4);
    }
#pragma unroll
    for (int cc = 0; cc < 2; cc++) {
        uint4 ua = make_uint4(pack_h2(pa[2*cc].x, pa[2*cc].y), pack_h2(pa[2*cc].z, pa[2*cc].w),
                              pack_h2(pa[2*cc+1].x, pa[2*cc+1].y), pack_h2(pa[2*cc+1].z, pa[2*cc+1].w));
        uint4 ub = make_uint4(pack_h2(pb[2*cc].x, pb[2*cc].y), pack_h2(pb[2*cc].z, pb[2*cc].w),
                              pack_h2(pb[2*cc+1].x, pb[2*cc+1].y), pack_h2(pb[2*cc+1].z, pb[2*cc+1].w));
        sts128(sta[cc], ua);
        sts128(stb[cc], ub);
    }
    __syncthreads();

    const int NT = K / GBK;   // 64
    for (int kt = 0; kt < NT; kt++) {
        const int buf = kt & 1;
        const uint32_t bofs = buf * GBUF;
        const bool more = (kt + 1 < NT);

        if (more) {
#pragma unroll
            for (int j = 0; j < 4; j++) {
                pa[j] = *(const float4*)(Ag + (kt + 1) * GBK + j * 4);
                pb[j] = *(const float4*)(Wg + (kt + 1) * GBK + j * 4);
            }
        }

#pragma unroll
        for (int ks = 0; ks < 2; ks++) {
            uint32_t af[4][4], bf[4][2];
#pragma unroll
            for (int mt = 0; mt < 4; mt++) {
                int chunk = 2 * ks + ahi;
                ldm_x4(af[mt], arow[mt] + bofs + (uint32_t)((chunk ^ axor[mt]) * 16));
            }
#pragma unroll
            for (int n2 = 0; n2 < 2; n2++) {
                int chunk = 2 * ks + bhi;
                uint32_t r[4];
                ldm_x4(r, brow[n2] + bofs + (uint32_t)((chunk ^ bxor[n2]) * 16));
                bf[n2*2][0] = r[0]; bf[n2*2][1] = r[1];
                bf[n2*2+1][0] = r[2]; bf[n2*2+1][1] = r[3];
            }
#pragma unroll
            for (int mt = 0; mt < 4; mt++)
#pragma unroll
                for (int nt = 0; nt < 4; nt++)
                    mma_fp16(acc[mt][nt], af[mt], bf[nt]);
        }

        if (more) {
            const uint32_t nofs = (buf ^ 1) * GBUF;
#pragma unroll
            for (int cc = 0; cc < 2; cc++) {
                uint4 ua = make_uint4(pack_h2(pa[2*cc].x, pa[2*cc].y), pack_h2(pa[2*cc].z, pa[2*cc].w),
                                      pack_h2(pa[2*cc+1].x, pa[2*cc+1].y), pack_h2(pa[2*cc+1].z, pa[2*cc+1].w));
                uint4 ub = make_uint4(pack_h2(pb[2*cc].x, pb[2*cc].y), pack_h2(pb[2*cc].z, pb[2*cc].w),
                                      pack_h2(pb[2*cc+1].x, pb[2*cc+1].y), pack_h2(pb[2*cc+1].z, pb[2*cc+1].w));
                sts128(sta[cc] + nofs, ua);
                sts128(stb[cc] + nofs, ub);
            }
        }
        __syncthreads();
    }

    // epilogue
#pragma unroll
    for (int mt = 0; mt < 4; mt++) {
        int r0 = bm + wm + mt * 16 + gid;
#pragma unroll
        for (int nt = 0; nt < 4; nt++) {
            int c0 = bn + wn + nt * 8 + tig * 2;
            *(float2*)&C[(size_t)r0 * N + c0]       = make_float2(acc[mt][nt][0], acc[mt][nt][1]);
            *(float2*)&C[(size_t)(r0 + 8) * N + c0] = make_float2(acc[mt][nt][2], acc[mt][nt][3]);
        }
    }
}

// ---------------------------------------------------------------------------
// counts
// ---------------------------------------------------------------------------
__global__ __launch_bounds__(256) void counts_kernel(
    const float* __restrict__ mask, float* __restrict__ cnt)
{
    __shared__ float part[256];
    const int b = blockIdx.x;
    const int t = threadIdx.x;
    const int base = b * Sc;

    float local[8];
    float sum = 0.f;
#pragma unroll
    for (int j = 0; j < 8; j++) {
        int s = t * 8 + j;
        float kp = (mask[base + s] == 0.f) ? 1.f : 0.f;
        sum += kp;
        local[j] = sum;
    }
    part[t] = sum;
    __syncthreads();
    if (t == 0) {
        float run = 0.f;
        for (int i = 0; i < 256; i++) { float tmp = part[i]; part[i] = run; run += tmp; }
    }
    __syncthreads();
    float off = part[t];
#pragma unroll
    for (int j = 0; j < 8; j++)
        cnt[base + t * 8 + j] = off + local[j];
}

// ---------------------------------------------------------------------------
// fused post-projection: RoPE+L2norm+mask for Q and K, scaling for V
// ---------------------------------------------------------------------------
__global__ __launch_bounds__(128) void post_qkv_kernel(
    float* __restrict__ Q, float* __restrict__ K, float* __restrict__ V,
    const float* __restrict__ mask, const int* __restrict__ pos,
    const float* __restrict__ cnt, const float* __restrict__ nc)
{
    const int bsh = blockIdx.x;
    const int h  = bsh & (Hc - 1);
    const int bs = bsh >> 4;
    const int d = threadIdx.x;
    const size_t off = (size_t)bs * Dc + h * HDc + d;

    __shared__ float sq[HDc], sk[HDc];
    __shared__ float redq[4], redk[4];

    float xq = Q[off], xk = K[off];
    sq[d] = xq; sk[d] = xk;
    __syncthreads();

    float yq = xq, yk = xk;
    if (d < ROTc) {
        int i = d >> 1;
        float inv = powf(10000.f, -(float)(2 * i) / (float)ROTc);
        float ang = (float)pos[bs] * inv;
        float sn, cs;
        sincosf(ang, &sn, &cs);
        float oq = (d & 1) ? sq[d - 1] : sq[d + 1];
        float ok = (d & 1) ? sk[d - 1] : sk[d + 1];
        yq = (d & 1) ? (xq * cs + oq * sn) : (xq * cs - oq * sn);
        yk = (d & 1) ? (xk * cs + ok * sn) : (xk * cs - ok * sn);
    }

    float ssq = yq * yq, ssk = yk * yk;
#pragma unroll
    for (int o = 16; o; o >>= 1) {
        ssq += __shfl_xor_sync(0xffffffffu, ssq, o);
        ssk += __shfl_xor_sync(0xffffffffu, ssk, o);
    }
    if ((d & 31) == 0) { redq[d >> 5] = ssq; redk[d >> 5] = ssk; }
    __syncthreads();
    float nq = sqrtf(redq[0] + redq[1] + redq[2] + redq[3]);
    float nk = sqrtf(redk[0] + redk[1] + redk[2] + redk[3]);

    float keep = (mask[bs] == 0.f) ? 1.f : 0.f;
    Q[off] = yq / fmaxf(nq, 1e-12f) * keep;
    K[off] = yk / fmaxf(nk, 1e-12f) * keep;

    float expo = 1.f / (1.f + expf(-nc[h]));
    float scale = keep / fmaxf(powf(cnt[bs], expo), 1.f);
    V[off] *= scale;
}

// ---------------------------------------------------------------------------
// Tensor-core causal attention (tf32), unchanged (passing since R4)
// ---------------------------------------------------------------------------
#define AQT 64
#define AKT 64
#define QP  132
#define VP  136
#define PP  68
#define QS_OFF 0
#define KS_OFF (AQT*QP)
#define VS_OFF (KS_OFF + AKT*QP)
#define PS_OFF (VS_OFF + AKT*VP)
#define ATTN_U32 (PS_OFF + AQT*PP)
#define ATTN_SMEM (ATTN_U32 * 4)

__global__ __launch_bounds__(256) void attn_tc_kernel(
    const float* __restrict__ Q, const float* __restrict__ Kb,
    const float* __restrict__ V, float* __restrict__ O)
{
    extern __shared__ uint32_t sm[];
    uint32_t* Qs = sm + QS_OFF;
    uint32_t* Ks = sm + KS_OFF;
    uint32_t* Vs = sm + VS_OFF;
    uint32_t* Ps = sm + PS_OFF;

    const int bh = blockIdx.y;
    const int b = bh >> 4;
    const int h = bh & (Hc - 1);
    const int qt = blockIdx.x;

    const int tid  = threadIdx.x;
    const int warp = tid >> 5, lane = tid & 31;
    const int gid  = lane >> 2, tig = lane & 3;
    const int wq   = (warp >> 1) * 16;
    const int wk1  = (warp & 1) * 32;
    const int wd2  = (warp & 1) * 64;

    const float* Qg = Q + ((size_t)(b * Sc + qt * AQT)) * Dc + h * HDc;

    for (int idx = tid; idx < AQT * 32; idx += 256) {
        int r = idx >> 5, c4 = (idx & 31) * 4;
        float4 v = *(const float4*)(Qg + (size_t)r * Dc + c4);
        *(uint4*)&Qs[r * QP + c4] =
            make_uint4(f2tf32(v.x), f2tf32(v.y), f2tf32(v.z), f2tf32(v.w));
    }

    float oacc[8][4];
#pragma unroll
    for (int i = 0; i < 8; i++)
#pragma unroll
        for (int l = 0; l < 4; l++) oacc[i][l] = 0.f;

    for (int kt = 0; kt <= qt; kt++) {
        const float* Kg = Kb + ((size_t)(b * Sc + kt * AKT)) * Dc + h * HDc;
        const float* Vg = V  + ((size_t)(b * Sc + kt * AKT)) * Dc + h * HDc;

        __syncthreads();
        for (int idx = tid; idx < AKT * 32; idx += 256) {
            int r = idx >> 5, c4 = (idx & 31) * 4;
            float4 kv = *(const float4*)(Kg + (size_t)r * Dc + c4);
            float4 vv = *(const float4*)(Vg + (size_t)r * Dc + c4);
            *(uint4*)&Ks[r * QP + c4] =
                make_uint4(f2tf32(kv.x), f2tf32(kv.y), f2tf32(kv.z), f2tf32(kv.w));
            *(uint4*)&Vs[r * VP + c4] =
                make_uint4(f2tf32(vv.x), f2tf32(vv.y), f2tf32(vv.z), f2tf32(vv.w));
        }
        __syncthreads();

        float pacc[4][4];
#pragma unroll
        for (int i = 0; i < 4; i++)
#pragma unroll
            for (int l = 0; l < 4; l++) pacc[i][l] = 0.f;

#pragma unroll
        for (int ks = 0; ks < 16; ks++) {
            const int kb = ks * 8;
            uint32_t a[4];
            int r0 = wq + gid, r1 = r0 + 8;
            a[0] = Qs[r0 * QP + kb + tig];
            a[1] = Qs[r1 * QP + kb + tig];
            a[2] = Qs[r0 * QP + kb + 4 + tig];
            a[3] = Qs[r1 * QP + kb + 4 + tig];
#pragma unroll
            for (int nt = 0; nt < 4; nt++) {
                int rn = wk1 + nt * 8 + gid;
                uint32_t bfr[2];
                bfr[0] = Ks[rn * QP + kb + tig];
                bfr[1] = Ks[rn * QP + kb + 4 + tig];
                mma_tf32(pacc[nt], a, bfr);
            }
        }

        const bool diag = (kt == qt);
#pragma unroll
        for (int nt = 0; nt < 4; nt++) {
            int kl0 = wk1 + nt * 8 + tig * 2;
            int q0 = wq + gid, q1 = q0 + 8;
            float v00 = pacc[nt][0], v01 = pacc[nt][1];
            float v10 = pacc[nt][2], v11 = pacc[nt][3];
            if (diag) {
                if (kl0     > q0) v00 = 0.f;
                if (kl0 + 1 > q0) v01 = 0.f;
                if (kl0     > q1) v10 = 0.f;
                if (kl0 + 1 > q1) v11 = 0.f;
            }
            Ps[q0 * PP + kl0]     = f2tf32(v00);
            Ps[q0 * PP + kl0 + 1] = f2tf32(v01);
            Ps[q1 * PP + kl0]     = f2tf32(v10);
            Ps[q1 * PP + kl0 + 1] = f2tf32(v11);
        }
        __syncthreads();

#pragma unroll
        for (int ks = 0; ks < 8; ks++) {
            const int kb = ks * 8;
            uint32_t a[4];
            int r0 = wq + gid, r1 = r0 + 8;
            a[0] = Ps[r0 * PP + kb + tig];
            a[1] = Ps[r1 * PP + kb + tig];
            a[2] = Ps[r0 * PP + kb + 4 + tig];
            a[3] = Ps[r1 * PP + kb + 4 + tig];
#pragma unroll
            for (int nt = 0; nt < 8; nt++) {
                int dcol = wd2 + nt * 8 + gid;
                uint32_t bfr[2];
                bfr[0] = Vs[(kb + tig)     * VP + dcol];
                bfr[1] = Vs[(kb + 4 + tig) * VP + dcol];
                mma_tf32(oacc[nt], a, bfr);
            }
        }
    }

    float* Og = O + ((size_t)(b * Sc + qt * AQT)) * Dc + h * HDc;
    int q0 = wq + gid, q1 = q0 + 8;
#pragma unroll
    for (int nt = 0; nt < 8; nt++) {
        int d0 = wd2 + nt * 8 + tig * 2;
        *(float2*)&Og[(size_t)q0 * Dc + d0] = make_float2(oacc[nt][0], oacc[nt][1]);
        *(float2*)&Og[(size_t)q1 * Dc + d0] = make_float2(oacc[nt][2], oacc[nt][3]);
    }
}

// ---------------------------------------------------------------------------
// launch
// ---------------------------------------------------------------------------
extern "C" void kernel_launch(void* const* d_in, const int* in_sizes, int n_in,
                              void* d_out, int out_size)
{
    const float* hs   = (const float*)d_in[0];
    const float* mask = (const float*)d_in[1];
    const int*   pos  = (const int*)  d_in[2];
    const float* Wq   = (const float*)d_in[3];
    const float* Wk   = (const float*)d_in[4];
    const float* Wv   = (const float*)d_in[5];
    const float* Wo   = (const float*)d_in[6];
    const float* nc   = (const float*)d_in[7];
    float* out = (float*)d_out;

    float *q, *k, *v, *ab, *cnt;
    cudaGetSymbolAddress((void**)&q,   g_q);
    cudaGetSymbolAddress((void**)&k,   g_k);
    cudaGetSymbolAddress((void**)&v,   g_v);
    cudaGetSymbolAddress((void**)&ab,  g_ab);
    cudaGetSymbolAddress((void**)&cnt, g_cnt);

    cudaFuncSetAttribute(attn_tc_kernel,
                         cudaFuncAttributeMaxDynamicSharedMemorySize, ATTN_SMEM);

    dim3 gemmGrid(Dc / GBN, Mc / GBM);   // (16, 32)

    counts_kernel<<<Bc, 256>>>(mask, cnt);

    gemm_fp16<<<gemmGrid, 256>>>(hs, Wq, q, Mc, Dc, Dc);
    gemm_fp16<<<gemmGrid, 256>>>(hs, Wk, k, Mc, Dc, Dc);
    gemm_fp16<<<gemmGrid, 256>>>(hs, Wv, v, Mc, Dc, Dc);

    const int nrows = Bc * Sc * Hc;      // 65536
    post_qkv_kernel<<<nrows, 128>>>(q, k, v, mask, pos, cnt, nc);

    dim3 attnGrid(Sc / AQT, Bc * Hc);    // (32, 32)
    attn_tc_kernel<<<attnGrid, 256, ATTN_SMEM>>>(q, k, v, ab);

    gemm_fp16<<<gemmGrid, 256>>>(ab, Wo, out, Mc, Dc, Dc);
}

// round 7
// speedup vs baseline: 4.5328x; 1.2685x over previous
#include <cuda_runtime.h>
#include <cuda_fp16.h>
#include <math.h>
#include <stdint.h>

// Problem constants
#define Bc   2
#define Sc   2048
#define Dc   2048
#define Hc   16
#define HDc  128
#define ROTc 64
#define Mc   (Bc*Sc)

// ---------------------------------------------------------------------------
// Scratch
// ---------------------------------------------------------------------------
__device__ float g_q [(size_t)Bc*Sc*Dc];
__device__ float g_k [(size_t)Bc*Sc*Dc];
__device__ float g_v [(size_t)Bc*Sc*Dc];
__device__ float g_cnt[Bc*Sc];
__device__ half  g_hsh[(size_t)Mc*Dc];
__device__ half  g_wqh[(size_t)Dc*Dc];
__device__ half  g_wkh[(size_t)Dc*Dc];
__device__ half  g_wvh[(size_t)Dc*Dc];
__device__ half  g_woh[(size_t)Dc*Dc];
__device__ half  g_abh[(size_t)Mc*Dc];

// ---------------------------------------------------------------------------
// helpers
// ---------------------------------------------------------------------------
__device__ __forceinline__ uint32_t smem_u32(const void* p) {
    uint32_t a;
    asm("{ .reg .u64 t; cvta.to.shared.u64 t, %1; cvt.u32.u64 %0, t; }"
        : "=r"(a) : "l"(p));
    return a;
}
__device__ __forceinline__ uint32_t f2tf32(float x) {
    uint32_t u;
    asm("cvt.rna.tf32.f32 %0, %1;" : "=r"(u) : "f"(x));
    return u;
}
__device__ __forceinline__ uint32_t pack_h2(float lo, float hi) {
    half2 h = __floats2half2_rn(lo, hi);
    return *(uint32_t*)&h;
}
__device__ __forceinline__ void cp16(uint32_t dst, const void* src) {
    asm volatile("cp.async.cg.shared.global [%0], [%1], 16;" :: "r"(dst), "l"(src));
}
#define CP_COMMIT() asm volatile("cp.async.commit_group;" ::: "memory")
template<int N>
__device__ __forceinline__ void cp_wait() {
    asm volatile("cp.async.wait_group %0;" :: "n"(N) : "memory");
}
__device__ __forceinline__ void ldm_x4(uint32_t r[4], uint32_t addr) {
    asm volatile("ldmatrix.sync.aligned.m8n8.x4.shared.b16 {%0,%1,%2,%3}, [%4];"
        : "=r"(r[0]), "=r"(r[1]), "=r"(r[2]), "=r"(r[3]) : "r"(addr));
}
__device__ __forceinline__ void mma_fp16(float c[4], const uint32_t a[4],
                                         const uint32_t b[2]) {
    asm volatile(
        "mma.sync.aligned.m16n8k16.row.col.f32.f16.f16.f32 "
        "{%0,%1,%2,%3}, {%4,%5,%6,%7}, {%8,%9}, {%0,%1,%2,%3};"
        : "+f"(c[0]), "+f"(c[1]), "+f"(c[2]), "+f"(c[3])
        : "r"(a[0]), "r"(a[1]), "r"(a[2]), "r"(a[3]),
          "r"(b[0]), "r"(b[1]));
}
__device__ __forceinline__ void mma_tf32(float c[4], const uint32_t a[4],
                                         const uint32_t b[2]) {
    asm volatile(
        "mma.sync.aligned.m16n8k8.row.col.f32.tf32.tf32.f32 "
        "{%0,%1,%2,%3}, {%4,%5,%6,%7}, {%8,%9}, {%0,%1,%2,%3};"
        : "+f"(c[0]), "+f"(c[1]), "+f"(c[2]), "+f"(c[3])
        : "r"(a[0]), "r"(a[1]), "r"(a[2]), "r"(a[3]),
          "r"(b[0]), "r"(b[1]));
}

// ---------------------------------------------------------------------------
// fp32 -> fp16 conversion (grid-stride, 8 elems/thread)
// ---------------------------------------------------------------------------
__global__ __launch_bounds__(256) void f32_to_f16(
    const float* __restrict__ src, half* __restrict__ dst, int n)
{
    int i = (blockIdx.x * 256 + threadIdx.x) * 8;
    for (; i < n; i += gridDim.x * 256 * 8) {
        float4 a = *(const float4*)(src + i);
        float4 b = *(const float4*)(src + i + 4);
        uint4 u = make_uint4(pack_h2(a.x, a.y), pack_h2(a.z, a.w),
                             pack_h2(b.x, b.y), pack_h2(b.z, b.w));
        *(uint4*)(dst + i) = u;
    }
}

// ---------------------------------------------------------------------------
// fp16 tensor-core GEMM with cp.async 3-stage pipeline.
// C[M,N](fp32) = A[M,K](fp16) * W[N,K](fp16)^T.
// 128x128 block, BK=32, 256 thr / 8 warps (warp tile 64x32).
// Swizzle: 64B rows, 16B chunk c at phys = c ^ ((row>>1)&3).
// ---------------------------------------------------------------------------
#define GBM 128
#define GBN 128
#define GBK 32
#define GBUF 8192
#define STAGES 3

__global__ __launch_bounds__(256, 2) void gemm_fp16(
    const half* __restrict__ A, const half* __restrict__ W,
    float* __restrict__ C, int M, int N, int K)
{
    __shared__ half As[STAGES][GBM][GBK];
    __shared__ half Bs[STAGES][GBN][GBK];

    const int tid  = threadIdx.x;
    const int warp = tid >> 5, lane = tid & 31;
    const int gid  = lane >> 2, tig = lane & 3;
    const int wm   = (warp >> 2) * 64, wn = (warp & 3) * 32;
    const int bm   = blockIdx.y * GBM,  bn = blockIdx.x * GBN;

    const int lr = tid >> 1;
    const int lh = tid & 1;

    const half* Ag = A + (size_t)(bm + lr) * K + lh * 16;
    const half* Wg = W + (size_t)(bn + lr) * K + lh * 16;

    const uint32_t As0 = smem_u32(As);
    const uint32_t Bs0 = smem_u32(Bs);

    uint32_t sta[2], stb[2];
#pragma unroll
    for (int cc = 0; cc < 2; cc++) {
        int chunk = lh * 2 + cc;
        int phys = chunk ^ ((lr >> 1) & 3);
        sta[cc] = As0 + lr * 64 + phys * 16;
        stb[cc] = Bs0 + lr * 64 + phys * 16;
    }

    uint32_t arow[4]; int axor[4];
    const int ahi = lane >> 4;
#pragma unroll
    for (int mt = 0; mt < 4; mt++) {
        int r = wm + 16 * mt + (lane & 7) + ((lane >> 3) & 1) * 8;
        arow[mt] = As0 + r * 64;
        axor[mt] = (r >> 1) & 3;
    }
    uint32_t brow[2]; int bxor[2];
    const int bhi = (lane >> 3) & 1;
#pragma unroll
    for (int n2 = 0; n2 < 2; n2++) {
        int r = wn + n2 * 16 + (lane & 7) + ((lane >> 4) & 1) * 8;
        brow[n2] = Bs0 + r * 64;
        bxor[n2] = (r >> 1) & 3;
    }

    float acc[4][4][4];
#pragma unroll
    for (int i = 0; i < 4; i++)
#pragma unroll
        for (int j = 0; j < 4; j++)
#pragma unroll
            for (int l = 0; l < 4; l++) acc[i][j][l] = 0.f;

    const int NT = K / GBK;   // 64

    // prologue: stages 0,1
#pragma unroll
    for (int s = 0; s < 2; s++) {
        const uint32_t ofs = s * GBUF;
#pragma unroll
        for (int cc = 0; cc < 2; cc++) {
            cp16(sta[cc] + ofs, Ag + (size_t)s * GBK + cc * 8);
            cp16(stb[cc] + ofs, Wg + (size_t)s * GBK + cc * 8);
        }
        CP_COMMIT();
    }

    for (int kt = 0; kt < NT; kt++) {
        if (kt == NT - 1) cp_wait<0>(); else cp_wait<1>();
        __syncthreads();

        if (kt + 2 < NT) {
            const int s = kt + 2;
            const uint32_t ofs = (uint32_t)(s % STAGES) * GBUF;
#pragma unroll
            for (int cc = 0; cc < 2; cc++) {
                cp16(sta[cc] + ofs, Ag + (size_t)s * GBK + cc * 8);
                cp16(stb[cc] + ofs, Wg + (size_t)s * GBK + cc * 8);
            }
            CP_COMMIT();
        }

        const uint32_t bofs = (uint32_t)(kt % STAGES) * GBUF;
#pragma unroll
        for (int ks = 0; ks < 2; ks++) {
            uint32_t af[4][4], bf[4][2];
#pragma unroll
            for (int mt = 0; mt < 4; mt++) {
                int chunk = 2 * ks + ahi;
                ldm_x4(af[mt], arow[mt] + bofs + (uint32_t)((chunk ^ axor[mt]) * 16));
            }
#pragma unroll
            for (int n2 = 0; n2 < 2; n2++) {
                int chunk = 2 * ks + bhi;
                uint32_t r[4];
                ldm_x4(r, brow[n2] + bofs + (uint32_t)((chunk ^ bxor[n2]) * 16));
                bf[n2*2][0] = r[0]; bf[n2*2][1] = r[1];
                bf[n2*2+1][0] = r[2]; bf[n2*2+1][1] = r[3];
            }
#pragma unroll
            for (int mt = 0; mt < 4; mt++)
#pragma unroll
                for (int nt = 0; nt < 4; nt++)
                    mma_fp16(acc[mt][nt], af[mt], bf[nt]);
        }
    }

    // epilogue
#pragma unroll
    for (int mt = 0; mt < 4; mt++) {
        int r0 = bm + wm + mt * 16 + gid;
#pragma unroll
        for (int nt = 0; nt < 4; nt++) {
            int c0 = bn + wn + nt * 8 + tig * 2;
            *(float2*)&C[(size_t)r0 * N + c0]       = make_float2(acc[mt][nt][0], acc[mt][nt][1]);
            *(float2*)&C[(size_t)(r0 + 8) * N + c0] = make_float2(acc[mt][nt][2], acc[mt][nt][3]);
        }
    }
}

// ---------------------------------------------------------------------------
// counts
// ---------------------------------------------------------------------------
__global__ __launch_bounds__(256) void counts_kernel(
    const float* __restrict__ mask, float* __restrict__ cnt)
{
    __shared__ float part[256];
    const int b = blockIdx.x;
    const int t = threadIdx.x;
    const int base = b * Sc;

    float local[8];
    float sum = 0.f;
#pragma unroll
    for (int j = 0; j < 8; j++) {
        int s = t * 8 + j;
        float kp = (mask[base + s] == 0.f) ? 1.f : 0.f;
        sum += kp;
        local[j] = sum;
    }
    part[t] = sum;
    __syncthreads();
    if (t == 0) {
        float run = 0.f;
        for (int i = 0; i < 256; i++) { float tmp = part[i]; part[i] = run; run += tmp; }
    }
    __syncthreads();
    float off = part[t];
#pragma unroll
    for (int j = 0; j < 8; j++)
        cnt[base + t * 8 + j] = off + local[j];
}

// ---------------------------------------------------------------------------
// fused post-projection: RoPE+L2norm+mask for Q and K, scaling for V
// ---------------------------------------------------------------------------
__global__ __launch_bounds__(128) void post_qkv_kernel(
    float* __restrict__ Q, float* __restrict__ K, float* __restrict__ V,
    const float* __restrict__ mask, const int* __restrict__ pos,
    const float* __restrict__ cnt, const float* __restrict__ nc)
{
    const int bsh = blockIdx.x;
    const int h  = bsh & (Hc - 1);
    const int bs = bsh >> 4;
    const int d = threadIdx.x;
    const size_t off = (size_t)bs * Dc + h * HDc + d;

    __shared__ float sq[HDc], sk[HDc];
    __shared__ float redq[4], redk[4];

    float xq = Q[off], xk = K[off];
    sq[d] = xq; sk[d] = xk;
    __syncthreads();

    float yq = xq, yk = xk;
    if (d < ROTc) {
        int i = d >> 1;
        float inv = powf(10000.f, -(float)(2 * i) / (float)ROTc);
        float ang = (float)pos[bs] * inv;
        float sn, cs;
        sincosf(ang, &sn, &cs);
        float oq = (d & 1) ? sq[d - 1] : sq[d + 1];
        float ok = (d & 1) ? sk[d - 1] : sk[d + 1];
        yq = (d & 1) ? (xq * cs + oq * sn) : (xq * cs - oq * sn);
        yk = (d & 1) ? (xk * cs + ok * sn) : (xk * cs - ok * sn);
    }

    float ssq = yq * yq, ssk = yk * yk;
#pragma unroll
    for (int o = 16; o; o >>= 1) {
        ssq += __shfl_xor_sync(0xffffffffu, ssq, o);
        ssk += __shfl_xor_sync(0xffffffffu, ssk, o);
    }
    if ((d & 31) == 0) { redq[d >> 5] = ssq; redk[d >> 5] = ssk; }
    __syncthreads();
    float nq = sqrtf(redq[0] + redq[1] + redq[2] + redq[3]);
    float nk = sqrtf(redk[0] + redk[1] + redk[2] + redk[3]);

    float keep = (mask[bs] == 0.f) ? 1.f : 0.f;
    Q[off] = yq / fmaxf(nq, 1e-12f) * keep;
    K[off] = yk / fmaxf(nk, 1e-12f) * keep;

    float expo = 1.f / (1.f + expf(-nc[h]));
    float scale = keep / fmaxf(powf(cnt[bs], expo), 1.f);
    V[off] *= scale;
}

// ---------------------------------------------------------------------------
// Tensor-core causal attention (tf32). Writes O as fp16 for the Wo GEMM.
// ---------------------------------------------------------------------------
#define AQT 64
#define AKT 64
#define QP  132
#define VP  136
#define PP  68
#define QS_OFF 0
#define KS_OFF (AQT*QP)
#define VS_OFF (KS_OFF + AKT*QP)
#define PS_OFF (VS_OFF + AKT*VP)
#define ATTN_U32 (PS_OFF + AQT*PP)
#define ATTN_SMEM (ATTN_U32 * 4)

__global__ __launch_bounds__(256) void attn_tc_kernel(
    const float* __restrict__ Q, const float* __restrict__ Kb,
    const float* __restrict__ V, half* __restrict__ O)
{
    extern __shared__ uint32_t sm[];
    uint32_t* Qs = sm + QS_OFF;
    uint32_t* Ks = sm + KS_OFF;
    uint32_t* Vs = sm + VS_OFF;
    uint32_t* Ps = sm + PS_OFF;

    const int bh = blockIdx.y;
    const int b = bh >> 4;
    const int h = bh & (Hc - 1);
    const int qt = blockIdx.x;

    const int tid  = threadIdx.x;
    const int warp = tid >> 5, lane = tid & 31;
    const int gid  = lane >> 2, tig = lane & 3;
    const int wq   = (warp >> 1) * 16;
    const int wk1  = (warp & 1) * 32;
    const int wd2  = (warp & 1) * 64;

    const float* Qg = Q + ((size_t)(b * Sc + qt * AQT)) * Dc + h * HDc;

    for (int idx = tid; idx < AQT * 32; idx += 256) {
        int r = idx >> 5, c4 = (idx & 31) * 4;
        float4 v = *(const float4*)(Qg + (size_t)r * Dc + c4);
        *(uint4*)&Qs[r * QP + c4] =
            make_uint4(f2tf32(v.x), f2tf32(v.y), f2tf32(v.z), f2tf32(v.w));
    }

    float oacc[8][4];
#pragma unroll
    for (int i = 0; i < 8; i++)
#pragma unroll
        for (int l = 0; l < 4; l++) oacc[i][l] = 0.f;

    for (int kt = 0; kt <= qt; kt++) {
        const float* Kg = Kb + ((size_t)(b * Sc + kt * AKT)) * Dc + h * HDc;
        const float* Vg = V  + ((size_t)(b * Sc + kt * AKT)) * Dc + h * HDc;

        __syncthreads();
        for (int idx = tid; idx < AKT * 32; idx += 256) {
            int r = idx >> 5, c4 = (idx & 31) * 4;
            float4 kv = *(const float4*)(Kg + (size_t)r * Dc + c4);
            float4 vv = *(const float4*)(Vg + (size_t)r * Dc + c4);
            *(uint4*)&Ks[r * QP + c4] =
                make_uint4(f2tf32(kv.x), f2tf32(kv.y), f2tf32(kv.z), f2tf32(kv.w));
            *(uint4*)&Vs[r * VP + c4] =
                make_uint4(f2tf32(vv.x), f2tf32(vv.y), f2tf32(vv.z), f2tf32(vv.w));
        }
        __syncthreads();

        float pacc[4][4];
#pragma unroll
        for (int i = 0; i < 4; i++)
#pragma unroll
            for (int l = 0; l < 4; l++) pacc[i][l] = 0.f;

#pragma unroll
        for (int ks = 0; ks < 16; ks++) {
            const int kb = ks * 8;
            uint32_t a[4];
            int r0 = wq + gid, r1 = r0 + 8;
            a[0] = Qs[r0 * QP + kb + tig];
            a[1] = Qs[r1 * QP + kb + tig];
            a[2] = Qs[r0 * QP + kb + 4 + tig];
            a[3] = Qs[r1 * QP + kb + 4 + tig];
#pragma unroll
            for (int nt = 0; nt < 4; nt++) {
                int rn = wk1 + nt * 8 + gid;
                uint32_t bfr[2];
                bfr[0] = Ks[rn * QP + kb + tig];
                bfr[1] = Ks[rn * QP + kb + 4 + tig];
                mma_tf32(pacc[nt], a, bfr);
            }
        }

        const bool diag = (kt == qt);
#pragma unroll
        for (int nt = 0; nt < 4; nt++) {
            int kl0 = wk1 + nt * 8 + tig * 2;
            int q0 = wq + gid, q1 = q0 + 8;
            float v00 = pacc[nt][0], v01 = pacc[nt][1];
            float v10 = pacc[nt][2], v11 = pacc[nt][3];
            if (diag) {
                if (kl0     > q0) v00 = 0.f;
                if (kl0 + 1 > q0) v01 = 0.f;
                if (kl0     > q1) v10 = 0.f;
                if (kl0 + 1 > q1) v11 = 0.f;
            }
            Ps[q0 * PP + kl0]     = f2tf32(v00);
            Ps[q0 * PP + kl0 + 1] = f2tf32(v01);
            Ps[q1 * PP + kl0]     = f2tf32(v10);
            Ps[q1 * PP + kl0 + 1] = f2tf32(v11);
        }
        __syncthreads();

#pragma unroll
        for (int ks = 0; ks < 8; ks++) {
            const int kb = ks * 8;
            uint32_t a[4];
            int r0 = wq + gid, r1 = r0 + 8;
            a[0] = Ps[r0 * PP + kb + tig];
            a[1] = Ps[r1 * PP + kb + tig];
            a[2] = Ps[r0 * PP + kb + 4 + tig];
            a[3] = Ps[r1 * PP + kb + 4 + tig];
#pragma unroll
            for (int nt = 0; nt < 8; nt++) {
                int dcol = wd2 + nt * 8 + gid;
                uint32_t bfr[2];
                bfr[0] = Vs[(kb + tig)     * VP + dcol];
                bfr[1] = Vs[(kb + 4 + tig) * VP + dcol];
                mma_tf32(oacc[nt], a, bfr);
            }
        }
    }

    // epilogue: write O as fp16
    half* Og = O + ((size_t)(b * Sc + qt * AQT)) * Dc + h * HDc;
    int q0 = wq + gid, q1 = q0 + 8;
#pragma unroll
    for (int nt = 0; nt < 8; nt++) {
        int d0 = wd2 + nt * 8 + tig * 2;
        *(uint32_t*)&Og[(size_t)q0 * Dc + d0] = pack_h2(oacc[nt][0], oacc[nt][1]);
        *(uint32_t*)&Og[(size_t)q1 * Dc + d0] = pack_h2(oacc[nt][2], oacc[nt][3]);
    }
}

// ---------------------------------------------------------------------------
// launch
// ---------------------------------------------------------------------------
extern "C" void kernel_launch(void* const* d_in, const int* in_sizes, int n_in,
                              void* d_out, int out_size)
{
    const float* hs   = (const float*)d_in[0];
    const float* mask = (const float*)d_in[1];
    const int*   pos  = (const int*)  d_in[2];
    const float* Wq   = (const float*)d_in[3];
    const float* Wk   = (const float*)d_in[4];
    const float* Wv   = (const float*)d_in[5];
    const float* Wo   = (const float*)d_in[6];
    const float* nc   = (const float*)d_in[7];
    float* out = (float*)d_out;

    float *q, *k, *v, *cnt;
    half *hsh, *wqh, *wkh, *wvh, *woh, *abh;
    cudaGetSymbolAddress((void**)&q,   g_q);
    cudaGetSymbolAddress((void**)&k,   g_k);
    cudaGetSymbolAddress((void**)&v,   g_v);
    cudaGetSymbolAddress((void**)&cnt, g_cnt);
    cudaGetSymbolAddress((void**)&hsh, g_hsh);
    cudaGetSymbolAddress((void**)&wqh, g_wqh);
    cudaGetSymbolAddress((void**)&wkh, g_wkh);
    cudaGetSymbolAddress((void**)&wvh, g_wvh);
    cudaGetSymbolAddress((void**)&woh, g_woh);
    cudaGetSymbolAddress((void**)&abh, g_abh);

    cudaFuncSetAttribute(attn_tc_kernel,
                         cudaFuncAttributeMaxDynamicSharedMemorySize, ATTN_SMEM);

    dim3 gemmGrid(Dc / GBN, Mc / GBM);   // (16, 32)
    const int nHS = Mc * Dc;             // 8M
    const int nW  = Dc * Dc;             // 4M

    counts_kernel<<<Bc, 256>>>(mask, cnt);

    f32_to_f16<<<nHS / (256 * 8), 256>>>(hs, hsh, nHS);
    f32_to_f16<<<nW  / (256 * 8), 256>>>(Wq, wqh, nW);
    f32_to_f16<<<nW  / (256 * 8), 256>>>(Wk, wkh, nW);
    f32_to_f16<<<nW  / (256 * 8), 256>>>(Wv, wvh, nW);
    f32_to_f16<<<nW  / (256 * 8), 256>>>(Wo, woh, nW);

    gemm_fp16<<<gemmGrid, 256>>>(hsh, wqh, q, Mc, Dc, Dc);
    gemm_fp16<<<gemmGrid, 256>>>(hsh, wkh, k, Mc, Dc, Dc);
    gemm_fp16<<<gemmGrid, 256>>>(hsh, wvh, v, Mc, Dc, Dc);

    const int nrows = Bc * Sc * Hc;      // 65536
    post_qkv_kernel<<<nrows, 128>>>(q, k, v, mask, pos, cnt, nc);

    dim3 attnGrid(Sc / AQT, Bc * Hc);    // (32, 32)
    attn_tc_kernel<<<attnGrid, 256, ATTN_SMEM>>>(q, k, v, abh);

    gemm_fp16<<<gemmGrid, 256>>>(abh, woh, out, Mc, Dc, Dc);
}

// round 8
// speedup vs baseline: 6.7484x; 1.4888x over previous
#include <cuda_runtime.h>
#include <cuda_fp16.h>
#include <math.h>
#include <stdint.h>

// Problem constants
#define Bc   2
#define Sc   2048
#define Dc   2048
#define Hc   16
#define HDc  128
#define ROTc 64
#define Mc   (Bc*Sc)

// ---------------------------------------------------------------------------
// Scratch
// ---------------------------------------------------------------------------
__device__ float g_q [(size_t)Bc*Sc*Dc];
__device__ float g_k [(size_t)Bc*Sc*Dc];
__device__ float g_v [(size_t)Bc*Sc*Dc];
__device__ float g_cnt[Bc*Sc];
__device__ half  g_hsh[(size_t)Mc*Dc];
__device__ half  g_wqh[(size_t)Dc*Dc];
__device__ half  g_wkh[(size_t)Dc*Dc];
__device__ half  g_wvh[(size_t)Dc*Dc];
__device__ half  g_woh[(size_t)Dc*Dc];
__device__ half  g_abh[(size_t)Mc*Dc];
__device__ half  g_qh [(size_t)Mc*Dc];
__device__ half  g_kh [(size_t)Mc*Dc];
__device__ half  g_vh [(size_t)Mc*Dc];

// ---------------------------------------------------------------------------
// helpers
// ---------------------------------------------------------------------------
__device__ __forceinline__ uint32_t smem_u32(const void* p) {
    uint32_t a;
    asm("{ .reg .u64 t; cvta.to.shared.u64 t, %1; cvt.u32.u64 %0, t; }"
        : "=r"(a) : "l"(p));
    return a;
}
__device__ __forceinline__ uint32_t pack_h2(float lo, float hi) {
    half2 h = __floats2half2_rn(lo, hi);
    return *(uint32_t*)&h;
}
__device__ __forceinline__ void cp16(uint32_t dst, const void* src) {
    asm volatile("cp.async.cg.shared.global [%0], [%1], 16;" :: "r"(dst), "l"(src));
}
#define CP_COMMIT() asm volatile("cp.async.commit_group;" ::: "memory")
template<int N>
__device__ __forceinline__ void cp_wait() {
    asm volatile("cp.async.wait_group %0;" :: "n"(N) : "memory");
}
__device__ __forceinline__ void ldm_x4(uint32_t r[4], uint32_t addr) {
    asm volatile("ldmatrix.sync.aligned.m8n8.x4.shared.b16 {%0,%1,%2,%3}, [%4];"
        : "=r"(r[0]), "=r"(r[1]), "=r"(r[2]), "=r"(r[3]) : "r"(addr));
}
__device__ __forceinline__ void ldm_x4t(uint32_t r[4], uint32_t addr) {
    asm volatile("ldmatrix.sync.aligned.m8n8.x4.trans.shared.b16 {%0,%1,%2,%3}, [%4];"
        : "=r"(r[0]), "=r"(r[1]), "=r"(r[2]), "=r"(r[3]) : "r"(addr));
}
__device__ __forceinline__ void sts32(uint32_t addr, uint32_t v) {
    asm volatile("st.shared.b32 [%0], %1;" :: "r"(addr), "r"(v));
}
__device__ __forceinline__ void mma_fp16(float c[4], const uint32_t a[4],
                                         const uint32_t b0, const uint32_t b1) {
    asm volatile(
        "mma.sync.aligned.m16n8k16.row.col.f32.f16.f16.f32 "
        "{%0,%1,%2,%3}, {%4,%5,%6,%7}, {%8,%9}, {%0,%1,%2,%3};"
        : "+f"(c[0]), "+f"(c[1]), "+f"(c[2]), "+f"(c[3])
        : "r"(a[0]), "r"(a[1]), "r"(a[2]), "r"(a[3]),
          "r"(b0), "r"(b1));
}

// ---------------------------------------------------------------------------
// fp32 -> fp16 conversion
// ---------------------------------------------------------------------------
__global__ __launch_bounds__(256) void f32_to_f16(
    const float* __restrict__ src, half* __restrict__ dst, int n)
{
    int i = (blockIdx.x * 256 + threadIdx.x) * 8;
    for (; i < n; i += gridDim.x * 256 * 8) {
        float4 a = *(const float4*)(src + i);
        float4 b = *(const float4*)(src + i + 4);
        uint4 u = make_uint4(pack_h2(a.x, a.y), pack_h2(a.z, a.w),
                             pack_h2(b.x, b.y), pack_h2(b.z, b.w));
        *(uint4*)(dst + i) = u;
    }
}

// ---------------------------------------------------------------------------
// fp16 tensor-core GEMM with cp.async 3-stage pipeline (unchanged from R7).
// ---------------------------------------------------------------------------
#define GBM 128
#define GBN 128
#define GBK 32
#define GBUF 8192
#define STAGES 3

__global__ __launch_bounds__(256, 2) void gemm_fp16(
    const half* __restrict__ A, const half* __restrict__ W,
    float* __restrict__ C, int M, int N, int K)
{
    __shared__ half As[STAGES][GBM][GBK];
    __shared__ half Bs[STAGES][GBN][GBK];

    const int tid  = threadIdx.x;
    const int warp = tid >> 5, lane = tid & 31;
    const int gid  = lane >> 2, tig = lane & 3;
    const int wm   = (warp >> 2) * 64, wn = (warp & 3) * 32;
    const int bm   = blockIdx.y * GBM,  bn = blockIdx.x * GBN;

    const int lr = tid >> 1;
    const int lh = tid & 1;

    const half* Ag = A + (size_t)(bm + lr) * K + lh * 16;
    const half* Wg = W + (size_t)(bn + lr) * K + lh * 16;

    const uint32_t As0 = smem_u32(As);
    const uint32_t Bs0 = smem_u32(Bs);

    uint32_t sta[2], stb[2];
#pragma unroll
    for (int cc = 0; cc < 2; cc++) {
        int chunk = lh * 2 + cc;
        int phys = chunk ^ ((lr >> 1) & 3);
        sta[cc] = As0 + lr * 64 + phys * 16;
        stb[cc] = Bs0 + lr * 64 + phys * 16;
    }

    uint32_t arow[4]; int axor[4];
    const int ahi = lane >> 4;
#pragma unroll
    for (int mt = 0; mt < 4; mt++) {
        int r = wm + 16 * mt + (lane & 7) + ((lane >> 3) & 1) * 8;
        arow[mt] = As0 + r * 64;
        axor[mt] = (r >> 1) & 3;
    }
    uint32_t brow[2]; int bxor[2];
    const int bhi = (lane >> 3) & 1;
#pragma unroll
    for (int n2 = 0; n2 < 2; n2++) {
        int r = wn + n2 * 16 + (lane & 7) + ((lane >> 4) & 1) * 8;
        brow[n2] = Bs0 + r * 64;
        bxor[n2] = (r >> 1) & 3;
    }

    float acc[4][4][4];
#pragma unroll
    for (int i = 0; i < 4; i++)
#pragma unroll
        for (int j = 0; j < 4; j++)
#pragma unroll
            for (int l = 0; l < 4; l++) acc[i][j][l] = 0.f;

    const int NT = K / GBK;

#pragma unroll
    for (int s = 0; s < 2; s++) {
        const uint32_t ofs = s * GBUF;
#pragma unroll
        for (int cc = 0; cc < 2; cc++) {
            cp16(sta[cc] + ofs, Ag + (size_t)s * GBK + cc * 8);
            cp16(stb[cc] + ofs, Wg + (size_t)s * GBK + cc * 8);
        }
        CP_COMMIT();
    }

    for (int kt = 0; kt < NT; kt++) {
        if (kt == NT - 1) cp_wait<0>(); else cp_wait<1>();
        __syncthreads();

        if (kt + 2 < NT) {
            const int s = kt + 2;
            const uint32_t ofs = (uint32_t)(s % STAGES) * GBUF;
#pragma unroll
            for (int cc = 0; cc < 2; cc++) {
                cp16(sta[cc] + ofs, Ag + (size_t)s * GBK + cc * 8);
                cp16(stb[cc] + ofs, Wg + (size_t)s * GBK + cc * 8);
            }
            CP_COMMIT();
        }

        const uint32_t bofs = (uint32_t)(kt % STAGES) * GBUF;
#pragma unroll
        for (int ks = 0; ks < 2; ks++) {
            uint32_t af[4][4], bf[4][2];
#pragma unroll
            for (int mt = 0; mt < 4; mt++) {
                int chunk = 2 * ks + ahi;
                ldm_x4(af[mt], arow[mt] + bofs + (uint32_t)((chunk ^ axor[mt]) * 16));
            }
#pragma unroll
            for (int n2 = 0; n2 < 2; n2++) {
                int chunk = 2 * ks + bhi;
                uint32_t r[4];
                ldm_x4(r, brow[n2] + bofs + (uint32_t)((chunk ^ bxor[n2]) * 16));
                bf[n2*2][0] = r[0]; bf[n2*2][1] = r[1];
                bf[n2*2+1][0] = r[2]; bf[n2*2+1][1] = r[3];
            }
#pragma unroll
            for (int mt = 0; mt < 4; mt++)
#pragma unroll
                for (int nt = 0; nt < 4; nt++)
                    mma_fp16(acc[mt][nt], af[mt], bf[nt][0], bf[nt][1]);
        }
    }

#pragma unroll
    for (int mt = 0; mt < 4; mt++) {
        int r0 = bm + wm + mt * 16 + gid;
#pragma unroll
        for (int nt = 0; nt < 4; nt++) {
            int c0 = bn + wn + nt * 8 + tig * 2;
            *(float2*)&C[(size_t)r0 * N + c0]       = make_float2(acc[mt][nt][0], acc[mt][nt][1]);
            *(float2*)&C[(size_t)(r0 + 8) * N + c0] = make_float2(acc[mt][nt][2], acc[mt][nt][3]);
        }
    }
}

// ---------------------------------------------------------------------------
// counts
// ---------------------------------------------------------------------------
__global__ __launch_bounds__(256) void counts_kernel(
    const float* __restrict__ mask, float* __restrict__ cnt)
{
    __shared__ float part[256];
    const int b = blockIdx.x;
    const int t = threadIdx.x;
    const int base = b * Sc;

    float local[8];
    float sum = 0.f;
#pragma unroll
    for (int j = 0; j < 8; j++) {
        int s = t * 8 + j;
        float kp = (mask[base + s] == 0.f) ? 1.f : 0.f;
        sum += kp;
        local[j] = sum;
    }
    part[t] = sum;
    __syncthreads();
    if (t == 0) {
        float run = 0.f;
        for (int i = 0; i < 256; i++) { float tmp = part[i]; part[i] = run; run += tmp; }
    }
    __syncthreads();
    float off = part[t];
#pragma unroll
    for (int j = 0; j < 8; j++)
        cnt[base + t * 8 + j] = off + local[j];
}

// ---------------------------------------------------------------------------
// fused post-projection: RoPE+L2norm+mask for Q/K, scale V; writes fp16
// ---------------------------------------------------------------------------
__global__ __launch_bounds__(128) void post_qkv_kernel(
    const float* __restrict__ Q, const float* __restrict__ K,
    const float* __restrict__ V,
    half* __restrict__ Qh, half* __restrict__ Kh, half* __restrict__ Vh,
    const float* __restrict__ mask, const int* __restrict__ pos,
    const float* __restrict__ cnt, const float* __restrict__ nc)
{
    const int bsh = blockIdx.x;
    const int h  = bsh & (Hc - 1);
    const int bs = bsh >> 4;
    const int d = threadIdx.x;
    const size_t off = (size_t)bs * Dc + h * HDc + d;

    __shared__ float sq[HDc], sk[HDc];
    __shared__ float redq[4], redk[4];

    float xq = Q[off], xk = K[off];
    sq[d] = xq; sk[d] = xk;
    __syncthreads();

    float yq = xq, yk = xk;
    if (d < ROTc) {
        int i = d >> 1;
        float inv = powf(10000.f, -(float)(2 * i) / (float)ROTc);
        float ang = (float)pos[bs] * inv;
        float sn, cs;
        sincosf(ang, &sn, &cs);
        float oq = (d & 1) ? sq[d - 1] : sq[d + 1];
        float ok = (d & 1) ? sk[d - 1] : sk[d + 1];
        yq = (d & 1) ? (xq * cs + oq * sn) : (xq * cs - oq * sn);
        yk = (d & 1) ? (xk * cs + ok * sn) : (xk * cs - ok * sn);
    }

    float ssq = yq * yq, ssk = yk * yk;
#pragma unroll
    for (int o = 16; o; o >>= 1) {
        ssq += __shfl_xor_sync(0xffffffffu, ssq, o);
        ssk += __shfl_xor_sync(0xffffffffu, ssk, o);
    }
    if ((d & 31) == 0) { redq[d >> 5] = ssq; redk[d >> 5] = ssk; }
    __syncthreads();
    float nq = sqrtf(redq[0] + redq[1] + redq[2] + redq[3]);
    float nk = sqrtf(redk[0] + redk[1] + redk[2] + redk[3]);

    float keep = (mask[bs] == 0.f) ? 1.f : 0.f;
    Qh[off] = __float2half(yq / fmaxf(nq, 1e-12f) * keep);
    Kh[off] = __float2half(yk / fmaxf(nk, 1e-12f) * keep);

    float expo = 1.f / (1.f + expf(-nc[h]));
    float scale = keep / fmaxf(powf(cnt[bs], expo), 1.f);
    Vh[off] = __float2half(V[off] * scale);
}

// ---------------------------------------------------------------------------
// fp16 tensor-core causal attention.
// 64q tile, 64k steps, HD=128. 256 thr / 8 warps.
// Q/K/V tiles: [64][128] half, 256B rows, swizzle phys = chunk ^ (row&7).
// P: [64][64] half, 128B rows, same swizzle law.
// cp.async double-buffered K/V.
// Phase1: P = Q.K^T (warp = 16q x 32k). Phase2: O += P.V (warp = 16q x 64d),
// V fragments via ldmatrix.x4.trans.
// ---------------------------------------------------------------------------
#define AQ2 64
#define ATT_QS 0u
#define ATT_KS0 16384u
#define ATT_KS1 32768u
#define ATT_VS0 49152u
#define ATT_VS1 65536u
#define ATT_PS 81920u
#define ATT_SMEM 90112

__global__ __launch_bounds__(256) void attn_fp16(
    const half* __restrict__ Qh, const half* __restrict__ Kh,
    const half* __restrict__ Vh, half* __restrict__ O)
{
    extern __shared__ half smh[];
    const uint32_t S0 = smem_u32(smh);

    const int bh = blockIdx.y;
    const int b = bh >> 4;
    const int h = bh & (Hc - 1);
    const int qt = blockIdx.x;

    const int tid  = threadIdx.x;
    const int warp = tid >> 5, lane = tid & 31;
    const int gid  = lane >> 2, tig = lane & 3;
    const int wq   = (warp >> 1) * 16;
    const int wk   = (warp & 1) * 32;
    const int wd   = (warp & 1) * 64;

    const uint32_t kbuf[2] = {ATT_KS0, ATT_KS1};
    const uint32_t vbuf[2] = {ATT_VS0, ATT_VS1};

    // per-thread staging chunks: cid = tid + 256*i, row = cid>>4, c = cid&15
    int srow[4], sphy[4];
#pragma unroll
    for (int i = 0; i < 4; i++) {
        int cid = tid + 256 * i;
        srow[i] = cid >> 4;
        int c = cid & 15;
        sphy[i] = c ^ (srow[i] & 7);
    }

    const half* Qg = Qh + ((size_t)(b * Sc + qt * AQ2)) * Dc + h * HDc;

    // prologue: stage Q + K/V tile 0
#pragma unroll
    for (int i = 0; i < 4; i++) {
        int c = (tid + 256 * i) & 15;
        cp16(S0 + ATT_QS + srow[i] * 256 + sphy[i] * 16,
             Qg + (size_t)srow[i] * Dc + c * 8);
    }
    {
        const half* Kg = Kh + ((size_t)(b * Sc)) * Dc + h * HDc;
        const half* Vg = Vh + ((size_t)(b * Sc)) * Dc + h * HDc;
#pragma unroll
        for (int i = 0; i < 4; i++) {
            int c = (tid + 256 * i) & 15;
            cp16(S0 + kbuf[0] + srow[i] * 256 + sphy[i] * 16,
                 Kg + (size_t)srow[i] * Dc + c * 8);
            cp16(S0 + vbuf[0] + srow[i] * 256 + sphy[i] * 16,
                 Vg + (size_t)srow[i] * Dc + c * 8);
        }
    }
    CP_COMMIT();

    float oacc[8][4];
#pragma unroll
    for (int i = 0; i < 8; i++)
#pragma unroll
        for (int l = 0; l < 4; l++) oacc[i][l] = 0.f;

    // ldmatrix bases
    const int arow1 = wq + (lane & 7) + ((lane >> 3) & 1) * 8;   // phase1/2 A row
    const int ax1 = arow1 & 7;
    const int chi = lane >> 4;                                   // chunk parity bit

    for (int kt = 0; kt <= qt; kt++) {
        cp_wait<0>();
        __syncthreads();

        if (kt + 1 <= qt) {
            const int s = kt + 1;
            const uint32_t kb = kbuf[s & 1], vb = vbuf[s & 1];
            const half* Kg = Kh + ((size_t)(b * Sc + s * AQ2)) * Dc + h * HDc;
            const half* Vg = Vh + ((size_t)(b * Sc + s * AQ2)) * Dc + h * HDc;
#pragma unroll
            for (int i = 0; i < 4; i++) {
                int c = (tid + 256 * i) & 15;
                cp16(S0 + kb + srow[i] * 256 + sphy[i] * 16,
                     Kg + (size_t)srow[i] * Dc + c * 8);
                cp16(S0 + vb + srow[i] * 256 + sphy[i] * 16,
                     Vg + (size_t)srow[i] * Dc + c * 8);
            }
            CP_COMMIT();
        }

        const uint32_t kbs = S0 + kbuf[kt & 1];
        const uint32_t vbs = S0 + vbuf[kt & 1];

        // ---- phase 1: P = Q.K^T ----
        float pacc[4][4];
#pragma unroll
        for (int i = 0; i < 4; i++)
#pragma unroll
            for (int l = 0; l < 4; l++) pacc[i][l] = 0.f;

#pragma unroll
        for (int ks = 0; ks < 8; ks++) {
            const int c0 = ks * 2 + chi;
            uint32_t a[4];
            ldm_x4(a, S0 + ATT_QS + arow1 * 256 + ((c0 ^ ax1) * 16));
#pragma unroll
            for (int n2 = 0; n2 < 2; n2++) {
                int brow = wk + n2 * 16 + (lane & 7) + ((lane >> 3) & 1) * 8;
                uint32_t r[4];
                ldm_x4(r, kbs + brow * 256 + ((c0 ^ (brow & 7)) * 16));
                mma_fp16(pacc[2*n2],   a, r[0], r[2]);
                mma_fp16(pacc[2*n2+1], a, r[1], r[3]);
            }
        }

        // mask diag + store P as fp16
        const bool diag = (kt == qt);
#pragma unroll
        for (int nt = 0; nt < 4; nt++) {
            int kl0 = wk + nt * 8 + tig * 2;
            int q0 = wq + gid, q1 = q0 + 8;
            float v00 = pacc[nt][0], v01 = pacc[nt][1];
            float v10 = pacc[nt][2], v11 = pacc[nt][3];
            if (diag) {
                if (kl0     > q0) v00 = 0.f;
                if (kl0 + 1 > q0) v01 = 0.f;
                if (kl0     > q1) v10 = 0.f;
                if (kl0 + 1 > q1) v11 = 0.f;
            }
            int chunk = kl0 >> 3;
            sts32(S0 + ATT_PS + q0 * 128 + ((chunk ^ (q0 & 7)) * 16) + tig * 4,
                  pack_h2(v00, v01));
            sts32(S0 + ATT_PS + q1 * 128 + ((chunk ^ (q1 & 7)) * 16) + tig * 4,
                  pack_h2(v10, v11));
        }
        __syncthreads();

        // ---- phase 2: O += P.V ----
#pragma unroll
        for (int ks = 0; ks < 4; ks++) {
            const int ca = ks * 2 + chi;          // P chunk (0..7)
            uint32_t a[4];
            ldm_x4(a, S0 + ATT_PS + arow1 * 128 + ((ca ^ ax1) * 16));
            const int vrow = ks * 16 + (lane & 7) + ((lane >> 3) & 1) * 8;
            const int vx = vrow & 7;
#pragma unroll
            for (int j = 0; j < 4; j++) {
                int cd = (wd >> 3) + j * 2 + chi;
                uint32_t r[4];
                ldm_x4t(r, vbs + vrow * 256 + ((cd ^ vx) * 16));
                mma_fp16(oacc[2*j],   a, r[0], r[1]);
                mma_fp16(oacc[2*j+1], a, r[2], r[3]);
            }
        }
        __syncthreads();   // done with P and this K/V buffer
    }

    // epilogue: write O as fp16
    half* Og = O + ((size_t)(b * Sc + qt * AQ2)) * Dc + h * HDc;
    int q0 = wq + gid, q1 = q0 + 8;
#pragma unroll
    for (int nt = 0; nt < 8; nt++) {
        int d0 = wd + nt * 8 + tig * 2;
        *(uint32_t*)&Og[(size_t)q0 * Dc + d0] = pack_h2(oacc[nt][0], oacc[nt][1]);
        *(uint32_t*)&Og[(size_t)q1 * Dc + d0] = pack_h2(oacc[nt][2], oacc[nt][3]);
    }
}

// ---------------------------------------------------------------------------
// launch
// ---------------------------------------------------------------------------
extern "C" void kernel_launch(void* const* d_in, const int* in_sizes, int n_in,
                              void* d_out, int out_size)
{
    const float* hs   = (const float*)d_in[0];
    const float* mask = (const float*)d_in[1];
    const int*   pos  = (const int*)  d_in[2];
    const float* Wq   = (const float*)d_in[3];
    const float* Wk   = (const float*)d_in[4];
    const float* Wv   = (const float*)d_in[5];
    const float* Wo   = (const float*)d_in[6];
    const float* nc   = (const float*)d_in[7];
    float* out = (float*)d_out;

    float *q, *k, *v, *cnt;
    half *hsh, *wqh, *wkh, *wvh, *woh, *abh, *qh, *kh, *vh;
    cudaGetSymbolAddress((void**)&q,   g_q);
    cudaGetSymbolAddress((void**)&k,   g_k);
    cudaGetSymbolAddress((void**)&v,   g_v);
    cudaGetSymbolAddress((void**)&cnt, g_cnt);
    cudaGetSymbolAddress((void**)&hsh, g_hsh);
    cudaGetSymbolAddress((void**)&wqh, g_wqh);
    cudaGetSymbolAddress((void**)&wkh, g_wkh);
    cudaGetSymbolAddress((void**)&wvh, g_wvh);
    cudaGetSymbolAddress((void**)&woh, g_woh);
    cudaGetSymbolAddress((void**)&abh, g_abh);
    cudaGetSymbolAddress((void**)&qh,  g_qh);
    cudaGetSymbolAddress((void**)&kh,  g_kh);
    cudaGetSymbolAddress((void**)&vh,  g_vh);

    cudaFuncSetAttribute(attn_fp16,
                         cudaFuncAttributeMaxDynamicSharedMemorySize, ATT_SMEM);

    dim3 gemmGrid(Dc / GBN, Mc / GBM);   // (16, 32)
    const int nHS = Mc * Dc;
    const int nW  = Dc * Dc;

    counts_kernel<<<Bc, 256>>>(mask, cnt);

    f32_to_f16<<<nHS / (256 * 8), 256>>>(hs, hsh, nHS);
    f32_to_f16<<<nW  / (256 * 8), 256>>>(Wq, wqh, nW);
    f32_to_f16<<<nW  / (256 * 8), 256>>>(Wk, wkh, nW);
    f32_to_f16<<<nW  / (256 * 8), 256>>>(Wv, wvh, nW);
    f32_to_f16<<<nW  / (256 * 8), 256>>>(Wo, woh, nW);

    gemm_fp16<<<gemmGrid, 256>>>(hsh, wqh, q, Mc, Dc, Dc);
    gemm_fp16<<<gemmGrid, 256>>>(hsh, wkh, k, Mc, Dc, Dc);
    gemm_fp16<<<gemmGrid, 256>>>(hsh, wvh, v, Mc, Dc, Dc);

    const int nrows = Bc * Sc * Hc;
    post_qkv_kernel<<<nrows, 128>>>(q, k, v, qh, kh, vh, mask, pos, cnt, nc);

    dim3 attnGrid(Sc / AQ2, Bc * Hc);    // (32, 32)
    attn_fp16<<<attnGrid, 256, ATT_SMEM>>>(qh, kh, vh, abh);

    gemm_fp16<<<gemmGrid, 256>>>(abh, woh, out, Mc, Dc, Dc);
}

// round 9
// speedup vs baseline: 7.1008x; 1.0522x over previous
#include <cuda_runtime.h>
#include <cuda_fp16.h>
#include <math.h>
#include <stdint.h>

// Problem constants
#define Bc   2
#define Sc   2048
#define Dc   2048
#define Hc   16
#define HDc  128
#define ROTc 64
#define Mc   (Bc*Sc)

// ---------------------------------------------------------------------------
// Scratch
// ---------------------------------------------------------------------------
__device__ float g_q [(size_t)Bc*Sc*Dc];
__device__ float g_k [(size_t)Bc*Sc*Dc];
__device__ float g_v [(size_t)Bc*Sc*Dc];
__device__ float g_cnt[Bc*Sc];
__device__ half  g_hsh[(size_t)Mc*Dc];
__device__ half  g_wqh[(size_t)Dc*Dc];
__device__ half  g_wkh[(size_t)Dc*Dc];
__device__ half  g_wvh[(size_t)Dc*Dc];
__device__ half  g_woh[(size_t)Dc*Dc];
__device__ half  g_abh[(size_t)Mc*Dc];
__device__ half  g_qh [(size_t)Mc*Dc];
__device__ half  g_kh [(size_t)Mc*Dc];
__device__ half  g_vh [(size_t)Mc*Dc];

// ---------------------------------------------------------------------------
// helpers
// ---------------------------------------------------------------------------
__device__ __forceinline__ uint32_t smem_u32(const void* p) {
    uint32_t a;
    asm("{ .reg .u64 t; cvta.to.shared.u64 t, %1; cvt.u32.u64 %0, t; }"
        : "=r"(a) : "l"(p));
    return a;
}
__device__ __forceinline__ uint32_t pack_h2(float lo, float hi) {
    half2 h = __floats2half2_rn(lo, hi);
    return *(uint32_t*)&h;
}
__device__ __forceinline__ void cp16(uint32_t dst, const void* src) {
    asm volatile("cp.async.cg.shared.global [%0], [%1], 16;" :: "r"(dst), "l"(src));
}
#define CP_COMMIT() asm volatile("cp.async.commit_group;" ::: "memory")
template<int N>
__device__ __forceinline__ void cp_wait() {
    asm volatile("cp.async.wait_group %0;" :: "n"(N) : "memory");
}
__device__ __forceinline__ void ldm_x4(uint32_t r[4], uint32_t addr) {
    asm volatile("ldmatrix.sync.aligned.m8n8.x4.shared.b16 {%0,%1,%2,%3}, [%4];"
        : "=r"(r[0]), "=r"(r[1]), "=r"(r[2]), "=r"(r[3]) : "r"(addr));
}
__device__ __forceinline__ void ldm_x4t(uint32_t r[4], uint32_t addr) {
    asm volatile("ldmatrix.sync.aligned.m8n8.x4.trans.shared.b16 {%0,%1,%2,%3}, [%4];"
        : "=r"(r[0]), "=r"(r[1]), "=r"(r[2]), "=r"(r[3]) : "r"(addr));
}
__device__ __forceinline__ void sts32(uint32_t addr, uint32_t v) {
    asm volatile("st.shared.b32 [%0], %1;" :: "r"(addr), "r"(v));
}
__device__ __forceinline__ void mma_fp16(float c[4], const uint32_t a[4],
                                         const uint32_t b0, const uint32_t b1) {
    asm volatile(
        "mma.sync.aligned.m16n8k16.row.col.f32.f16.f16.f32 "
        "{%0,%1,%2,%3}, {%4,%5,%6,%7}, {%8,%9}, {%0,%1,%2,%3};"
        : "+f"(c[0]), "+f"(c[1]), "+f"(c[2]), "+f"(c[3])
        : "r"(a[0]), "r"(a[1]), "r"(a[2]), "r"(a[3]),
          "r"(b0), "r"(b1));
}

// ---------------------------------------------------------------------------
// fp32 -> fp16 conversion
// ---------------------------------------------------------------------------
__global__ __launch_bounds__(256) void f32_to_f16(
    const float* __restrict__ src, half* __restrict__ dst, int n)
{
    int i = (blockIdx.x * 256 + threadIdx.x) * 8;
    for (; i < n; i += gridDim.x * 256 * 8) {
        float4 a = *(const float4*)(src + i);
        float4 b = *(const float4*)(src + i + 4);
        uint4 u = make_uint4(pack_h2(a.x, a.y), pack_h2(a.z, a.w),
                             pack_h2(b.x, b.y), pack_h2(b.z, b.w));
        *(uint4*)(dst + i) = u;
    }
}

// ---------------------------------------------------------------------------
// fp16 tensor-core GEMM, CTA tile 128x256, warp tile 64x64, BK=32,
// cp.async 3-stage pipeline, dynamic smem (72KB).
// Swizzle: 64B rows, 16B chunk c at phys = c ^ ((row>>1)&3).
// ---------------------------------------------------------------------------
#define GBM 128
#define GBN 256
#define GBK 32
#define GA_BUF 8192u            // 128 rows * 64B
#define GB_BUF 16384u           // 256 rows * 64B
#define GB_BASE (3u * GA_BUF)   // 24576
#define GEMM_SMEM (GB_BASE + 3u * GB_BUF)   // 73728
#define STAGES 3

__global__ __launch_bounds__(256) void gemm_fp16(
    const half* __restrict__ A, const half* __restrict__ W,
    float* __restrict__ C, int M, int N, int K)
{
    extern __shared__ half gsm[];
    const uint32_t S0 = smem_u32(gsm);

    const int tid  = threadIdx.x;
    const int warp = tid >> 5, lane = tid & 31;
    const int gid  = lane >> 2, tig = lane & 3;
    const int wm   = (warp >> 2) * 64, wn = (warp & 3) * 64;
    const int bm   = blockIdx.y * GBM,  bn = blockIdx.x * GBN;

    // staging: A 2 chunks/thread, B 4 chunks/thread (cid = tid + 256*i)
    int aRow[2], aC[2]; uint32_t aDst[2];
#pragma unroll
    for (int i = 0; i < 2; i++) {
        int cid = tid + 256 * i;
        aRow[i] = cid >> 2; aC[i] = cid & 3;
        int phys = aC[i] ^ ((aRow[i] >> 1) & 3);
        aDst[i] = S0 + aRow[i] * 64 + phys * 16;
    }
    int bRow[4], bC[4]; uint32_t bDst[4];
#pragma unroll
    for (int i = 0; i < 4; i++) {
        int cid = tid + 256 * i;
        bRow[i] = cid >> 2; bC[i] = cid & 3;
        int phys = bC[i] ^ ((bRow[i] >> 1) & 3);
        bDst[i] = S0 + GB_BASE + bRow[i] * 64 + phys * 16;
    }

    // ldmatrix bases
    uint32_t arow[4]; int axor[4];
    const int ahi = lane >> 4;
#pragma unroll
    for (int mt = 0; mt < 4; mt++) {
        int r = wm + 16 * mt + (lane & 7) + ((lane >> 3) & 1) * 8;
        arow[mt] = S0 + r * 64;
        axor[mt] = (r >> 1) & 3;
    }
    uint32_t brow[4]; int bxor[4];
    const int bhi = (lane >> 3) & 1;
#pragma unroll
    for (int n2 = 0; n2 < 4; n2++) {
        int r = wn + n2 * 16 + (lane & 7) + ((lane >> 4) & 1) * 8;
        brow[n2] = S0 + GB_BASE + r * 64;
        bxor[n2] = (r >> 1) & 3;
    }

    float acc[4][8][4];
#pragma unroll
    for (int i = 0; i < 4; i++)
#pragma unroll
        for (int j = 0; j < 8; j++)
#pragma unroll
            for (int l = 0; l < 4; l++) acc[i][j][l] = 0.f;

    const int NT = K / GBK;   // 64

    // prologue: stages 0,1
#pragma unroll
    for (int s = 0; s < 2; s++) {
#pragma unroll
        for (int i = 0; i < 2; i++)
            cp16(aDst[i] + s * GA_BUF,
                 A + (size_t)(bm + aRow[i]) * K + s * GBK + aC[i] * 8);
#pragma unroll
        for (int i = 0; i < 4; i++)
            cp16(bDst[i] + s * GB_BUF,
                 W + (size_t)(bn + bRow[i]) * K + s * GBK + bC[i] * 8);
        CP_COMMIT();
    }

    for (int kt = 0; kt < NT; kt++) {
        if (kt == NT - 1) cp_wait<0>(); else cp_wait<1>();
        __syncthreads();

        if (kt + 2 < NT) {
            const int s = kt + 2;
            const uint32_t sa = (uint32_t)(s % STAGES) * GA_BUF;
            const uint32_t sb = (uint32_t)(s % STAGES) * GB_BUF;
#pragma unroll
            for (int i = 0; i < 2; i++)
                cp16(aDst[i] + sa,
                     A + (size_t)(bm + aRow[i]) * K + s * GBK + aC[i] * 8);
#pragma unroll
            for (int i = 0; i < 4; i++)
                cp16(bDst[i] + sb,
                     W + (size_t)(bn + bRow[i]) * K + s * GBK + bC[i] * 8);
            CP_COMMIT();
        }

        const uint32_t aofs = (uint32_t)(kt % STAGES) * GA_BUF;
        const uint32_t bofs = (uint32_t)(kt % STAGES) * GB_BUF;
#pragma unroll
        for (int ks = 0; ks < 2; ks++) {
            uint32_t af[4][4], bf[8][2];
#pragma unroll
            for (int mt = 0; mt < 4; mt++) {
                int chunk = 2 * ks + ahi;
                ldm_x4(af[mt], arow[mt] + aofs + (uint32_t)((chunk ^ axor[mt]) * 16));
            }
#pragma unroll
            for (int n2 = 0; n2 < 4; n2++) {
                int chunk = 2 * ks + bhi;
                uint32_t r[4];
                ldm_x4(r, brow[n2] + bofs + (uint32_t)((chunk ^ bxor[n2]) * 16));
                bf[n2*2][0] = r[0]; bf[n2*2][1] = r[1];
                bf[n2*2+1][0] = r[2]; bf[n2*2+1][1] = r[3];
            }
#pragma unroll
            for (int mt = 0; mt < 4; mt++)
#pragma unroll
                for (int nt = 0; nt < 8; nt++)
                    mma_fp16(acc[mt][nt], af[mt], bf[nt][0], bf[nt][1]);
        }
    }

    // epilogue
#pragma unroll
    for (int mt = 0; mt < 4; mt++) {
        int r0 = bm + wm + mt * 16 + gid;
#pragma unroll
        for (int nt = 0; nt < 8; nt++) {
            int c0 = bn + wn + nt * 8 + tig * 2;
            *(float2*)&C[(size_t)r0 * N + c0]       = make_float2(acc[mt][nt][0], acc[mt][nt][1]);
            *(float2*)&C[(size_t)(r0 + 8) * N + c0] = make_float2(acc[mt][nt][2], acc[mt][nt][3]);
        }
    }
}

// ---------------------------------------------------------------------------
// counts
// ---------------------------------------------------------------------------
__global__ __launch_bounds__(256) void counts_kernel(
    const float* __restrict__ mask, float* __restrict__ cnt)
{
    __shared__ float part[256];
    const int b = blockIdx.x;
    const int t = threadIdx.x;
    const int base = b * Sc;

    float local[8];
    float sum = 0.f;
#pragma unroll
    for (int j = 0; j < 8; j++) {
        int s = t * 8 + j;
        float kp = (mask[base + s] == 0.f) ? 1.f : 0.f;
        sum += kp;
        local[j] = sum;
    }
    part[t] = sum;
    __syncthreads();
    if (t == 0) {
        float run = 0.f;
        for (int i = 0; i < 256; i++) { float tmp = part[i]; part[i] = run; run += tmp; }
    }
    __syncthreads();
    float off = part[t];
#pragma unroll
    for (int j = 0; j < 8; j++)
        cnt[base + t * 8 + j] = off + local[j];
}

// ---------------------------------------------------------------------------
// fused post-projection: RoPE+L2norm+mask for Q/K, scale V; writes fp16
// ---------------------------------------------------------------------------
__global__ __launch_bounds__(128) void post_qkv_kernel(
    const float* __restrict__ Q, const float* __restrict__ K,
    const float* __restrict__ V,
    half* __restrict__ Qh, half* __restrict__ Kh, half* __restrict__ Vh,
    const float* __restrict__ mask, const int* __restrict__ pos,
    const float* __restrict__ cnt, const float* __restrict__ nc)
{
    const int bsh = blockIdx.x;
    const int h  = bsh & (Hc - 1);
    const int bs = bsh >> 4;
    const int d = threadIdx.x;
    const size_t off = (size_t)bs * Dc + h * HDc + d;

    __shared__ float sq[HDc], sk[HDc];
    __shared__ float redq[4], redk[4];

    float xq = Q[off], xk = K[off];
    sq[d] = xq; sk[d] = xk;
    __syncthreads();

    float yq = xq, yk = xk;
    if (d < ROTc) {
        int i = d >> 1;
        float inv = powf(10000.f, -(float)(2 * i) / (float)ROTc);
        float ang = (float)pos[bs] * inv;
        float sn, cs;
        sincosf(ang, &sn, &cs);
        float oq = (d & 1) ? sq[d - 1] : sq[d + 1];
        float ok = (d & 1) ? sk[d - 1] : sk[d + 1];
        yq = (d & 1) ? (xq * cs + oq * sn) : (xq * cs - oq * sn);
        yk = (d & 1) ? (xk * cs + ok * sn) : (xk * cs - ok * sn);
    }

    float ssq = yq * yq, ssk = yk * yk;
#pragma unroll
    for (int o = 16; o; o >>= 1) {
        ssq += __shfl_xor_sync(0xffffffffu, ssq, o);
        ssk += __shfl_xor_sync(0xffffffffu, ssk, o);
    }
    if ((d & 31) == 0) { redq[d >> 5] = ssq; redk[d >> 5] = ssk; }
    __syncthreads();
    float nq = sqrtf(redq[0] + redq[1] + redq[2] + redq[3]);
    float nk = sqrtf(redk[0] + redk[1] + redk[2] + redk[3]);

    float keep = (mask[bs] == 0.f) ? 1.f : 0.f;
    Qh[off] = __float2half(yq / fmaxf(nq, 1e-12f) * keep);
    Kh[off] = __float2half(yk / fmaxf(nk, 1e-12f) * keep);

    float expo = 1.f / (1.f + expf(-nc[h]));
    float scale = keep / fmaxf(powf(cnt[bs], expo), 1.f);
    Vh[off] = __float2half(V[off] * scale);
}

// ---------------------------------------------------------------------------
// fp16 tensor-core causal attention (unchanged from R8)
// ---------------------------------------------------------------------------
#define AQ2 64
#define ATT_QS 0u
#define ATT_KS0 16384u
#define ATT_KS1 32768u
#define ATT_VS0 49152u
#define ATT_VS1 65536u
#define ATT_PS 81920u
#define ATT_SMEM 90112

__global__ __launch_bounds__(256) void attn_fp16(
    const half* __restrict__ Qh, const half* __restrict__ Kh,
    const half* __restrict__ Vh, half* __restrict__ O)
{
    extern __shared__ half smh[];
    const uint32_t S0 = smem_u32(smh);

    const int bh = blockIdx.y;
    const int b = bh >> 4;
    const int h = bh & (Hc - 1);
    const int qt = blockIdx.x;

    const int tid  = threadIdx.x;
    const int warp = tid >> 5, lane = tid & 31;
    const int gid  = lane >> 2, tig = lane & 3;
    const int wq   = (warp >> 1) * 16;
    const int wk   = (warp & 1) * 32;
    const int wd   = (warp & 1) * 64;

    const uint32_t kbuf[2] = {ATT_KS0, ATT_KS1};
    const uint32_t vbuf[2] = {ATT_VS0, ATT_VS1};

    int srow[4], sphy[4];
#pragma unroll
    for (int i = 0; i < 4; i++) {
        int cid = tid + 256 * i;
        srow[i] = cid >> 4;
        int c = cid & 15;
        sphy[i] = c ^ (srow[i] & 7);
    }

    const half* Qg = Qh + ((size_t)(b * Sc + qt * AQ2)) * Dc + h * HDc;

#pragma unroll
    for (int i = 0; i < 4; i++) {
        int c = (tid + 256 * i) & 15;
        cp16(S0 + ATT_QS + srow[i] * 256 + sphy[i] * 16,
             Qg + (size_t)srow[i] * Dc + c * 8);
    }
    {
        const half* Kg = Kh + ((size_t)(b * Sc)) * Dc + h * HDc;
        const half* Vg = Vh + ((size_t)(b * Sc)) * Dc + h * HDc;
#pragma unroll
        for (int i = 0; i < 4; i++) {
            int c = (tid + 256 * i) & 15;
            cp16(S0 + kbuf[0] + srow[i] * 256 + sphy[i] * 16,
                 Kg + (size_t)srow[i] * Dc + c * 8);
            cp16(S0 + vbuf[0] + srow[i] * 256 + sphy[i] * 16,
                 Vg + (size_t)srow[i] * Dc + c * 8);
        }
    }
    CP_COMMIT();

    float oacc[8][4];
#pragma unroll
    for (int i = 0; i < 8; i++)
#pragma unroll
        for (int l = 0; l < 4; l++) oacc[i][l] = 0.f;

    const int arow1 = wq + (lane & 7) + ((lane >> 3) & 1) * 8;
    const int ax1 = arow1 & 7;
    const int chi = lane >> 4;

    for (int kt = 0; kt <= qt; kt++) {
        cp_wait<0>();
        __syncthreads();

        if (kt + 1 <= qt) {
            const int s = kt + 1;
            const uint32_t kb = kbuf[s & 1], vb = vbuf[s & 1];
            const half* Kg = Kh + ((size_t)(b * Sc + s * AQ2)) * Dc + h * HDc;
            const half* Vg = Vh + ((size_t)(b * Sc + s * AQ2)) * Dc + h * HDc;
#pragma unroll
            for (int i = 0; i < 4; i++) {
                int c = (tid + 256 * i) & 15;
                cp16(S0 + kb + srow[i] * 256 + sphy[i] * 16,
                     Kg + (size_t)srow[i] * Dc + c * 8);
                cp16(S0 + vb + srow[i] * 256 + sphy[i] * 16,
                     Vg + (size_t)srow[i] * Dc + c * 8);
            }
            CP_COMMIT();
        }

        const uint32_t kbs = S0 + kbuf[kt & 1];
        const uint32_t vbs = S0 + vbuf[kt & 1];

        float pacc[4][4];
#pragma unroll
        for (int i = 0; i < 4; i++)
#pragma unroll
            for (int l = 0; l < 4; l++) pacc[i][l] = 0.f;

#pragma unroll
        for (int ks = 0; ks < 8; ks++) {
            const int c0 = ks * 2 + chi;
            uint32_t a[4];
            ldm_x4(a, S0 + ATT_QS + arow1 * 256 + ((c0 ^ ax1) * 16));
#pragma unroll
            for (int n2 = 0; n2 < 2; n2++) {
                int brow = wk + n2 * 16 + (lane & 7) + ((lane >> 3) & 1) * 8;
                uint32_t r[4];
                ldm_x4(r, kbs + brow * 256 + ((c0 ^ (brow & 7)) * 16));
                mma_fp16(pacc[2*n2],   a, r[0], r[2]);
                mma_fp16(pacc[2*n2+1], a, r[1], r[3]);
            }
        }

        const bool diag = (kt == qt);
#pragma unroll
        for (int nt = 0; nt < 4; nt++) {
            int kl0 = wk + nt * 8 + tig * 2;
            int q0 = wq + gid, q1 = q0 + 8;
            float v00 = pacc[nt][0], v01 = pacc[nt][1];
            float v10 = pacc[nt][2], v11 = pacc[nt][3];
            if (diag) {
                if (kl0     > q0) v00 = 0.f;
                if (kl0 + 1 > q0) v01 = 0.f;
                if (kl0     > q1) v10 = 0.f;
                if (kl0 + 1 > q1) v11 = 0.f;
            }
            int chunk = kl0 >> 3;
            sts32(S0 + ATT_PS + q0 * 128 + ((chunk ^ (q0 & 7)) * 16) + tig * 4,
                  pack_h2(v00, v01));
            sts32(S0 + ATT_PS + q1 * 128 + ((chunk ^ (q1 & 7)) * 16) + tig * 4,
                  pack_h2(v10, v11));
        }
        __syncthreads();

#pragma unroll
        for (int ks = 0; ks < 4; ks++) {
            const int ca = ks * 2 + chi;
            uint32_t a[4];
            ldm_x4(a, S0 + ATT_PS + arow1 * 128 + ((ca ^ ax1) * 16));
            const int vrow = ks * 16 + (lane & 7) + ((lane >> 3) & 1) * 8;
            const int vx = vrow & 7;
#pragma unroll
            for (int j = 0; j < 4; j++) {
                int cd = (wd >> 3) + j * 2 + chi;
                uint32_t r[4];
                ldm_x4t(r, vbs + vrow * 256 + ((cd ^ vx) * 16));
                mma_fp16(oacc[2*j],   a, r[0], r[1]);
                mma_fp16(oacc[2*j+1], a, r[2], r[3]);
            }
        }
        __syncthreads();
    }

    half* Og = O + ((size_t)(b * Sc + qt * AQ2)) * Dc + h * HDc;
    int q0 = wq + gid, q1 = q0 + 8;
#pragma unroll
    for (int nt = 0; nt < 8; nt++) {
        int d0 = wd + nt * 8 + tig * 2;
        *(uint32_t*)&Og[(size_t)q0 * Dc + d0] = pack_h2(oacc[nt][0], oacc[nt][1]);
        *(uint32_t*)&Og[(size_t)q1 * Dc + d0] = pack_h2(oacc[nt][2], oacc[nt][3]);
    }
}

// ---------------------------------------------------------------------------
// launch
// ---------------------------------------------------------------------------
extern "C" void kernel_launch(void* const* d_in, const int* in_sizes, int n_in,
                              void* d_out, int out_size)
{
    const float* hs   = (const float*)d_in[0];
    const float* mask = (const float*)d_in[1];
    const int*   pos  = (const int*)  d_in[2];
    const float* Wq   = (const float*)d_in[3];
    const float* Wk   = (const float*)d_in[4];
    const float* Wv   = (const float*)d_in[5];
    const float* Wo   = (const float*)d_in[6];
    const float* nc   = (const float*)d_in[7];
    float* out = (float*)d_out;

    float *q, *k, *v, *cnt;
    half *hsh, *wqh, *wkh, *wvh, *woh, *abh, *qh, *kh, *vh;
    cudaGetSymbolAddress((void**)&q,   g_q);
    cudaGetSymbolAddress((void**)&k,   g_k);
    cudaGetSymbolAddress((void**)&v,   g_v);
    cudaGetSymbolAddress((void**)&cnt, g_cnt);
    cudaGetSymbolAddress((void**)&hsh, g_hsh);
    cudaGetSymbolAddress((void**)&wqh, g_wqh);
    cudaGetSymbolAddress((void**)&wkh, g_wkh);
    cudaGetSymbolAddress((void**)&wvh, g_wvh);
    cudaGetSymbolAddress((void**)&woh, g_woh);
    cudaGetSymbolAddress((void**)&abh, g_abh);
    cudaGetSymbolAddress((void**)&qh,  g_qh);
    cudaGetSymbolAddress((void**)&kh,  g_kh);
    cudaGetSymbolAddress((void**)&vh,  g_vh);

    cudaFuncSetAttribute(gemm_fp16,
                         cudaFuncAttributeMaxDynamicSharedMemorySize, GEMM_SMEM);
    cudaFuncSetAttribute(attn_fp16,
                         cudaFuncAttributeMaxDynamicSharedMemorySize, ATT_SMEM);

    dim3 gemmGrid(Dc / GBN, Mc / GBM);   // (8, 32)
    const int nHS = Mc * Dc;
    const int nW  = Dc * Dc;

    counts_kernel<<<Bc, 256>>>(mask, cnt);

    f32_to_f16<<<nHS / (256 * 8), 256>>>(hs, hsh, nHS);
    f32_to_f16<<<nW  / (256 * 8), 256>>>(Wq, wqh, nW);
    f32_to_f16<<<nW  / (256 * 8), 256>>>(Wk, wkh, nW);
    f32_to_f16<<<nW  / (256 * 8), 256>>>(Wv, wvh, nW);
    f32_to_f16<<<nW  / (256 * 8), 256>>>(Wo, woh, nW);

    gemm_fp16<<<gemmGrid, 256, GEMM_SMEM>>>(hsh, wqh, q, Mc, Dc, Dc);
    gemm_fp16<<<gemmGrid, 256, GEMM_SMEM>>>(hsh, wkh, k, Mc, Dc, Dc);
    gemm_fp16<<<gemmGrid, 256, GEMM_SMEM>>>(hsh, wvh, v, Mc, Dc, Dc);

    const int nrows = Bc * Sc * Hc;
    post_qkv_kernel<<<nrows, 128>>>(q, k, v, qh, kh, vh, mask, pos, cnt, nc);

    dim3 attnGrid(Sc / AQ2, Bc * Hc);    // (32, 32)
    attn_fp16<<<attnGrid, 256, ATT_SMEM>>>(qh, kh, vh, abh);

    gemm_fp16<<<gemmGrid, 256, GEMM_SMEM>>>(abh, woh, out, Mc, Dc, Dc);
}

// round 10
// speedup vs baseline: 7.2903x; 1.0267x over previous
#include <cuda_runtime.h>
#include <cuda_fp16.h>
#include <math.h>
#include <stdint.h>

// Problem constants
#define Bc   2
#define Sc   2048
#define Dc   2048
#define Hc   16
#define HDc  128
#define ROTc 64
#define Mc   (Bc*Sc)
#define NQKV (3*Dc)   // 6144

// ---------------------------------------------------------------------------
// Scratch
// ---------------------------------------------------------------------------
__device__ float g_cnt[Bc*Sc];
__device__ half  g_hsh [(size_t)Mc*Dc];
__device__ half  g_wh  [(size_t)NQKV*Dc];   // packed [Wq;Wk;Wv], row-major [6144][2048]
__device__ half  g_woh [(size_t)Dc*Dc];
__device__ half  g_qkvh[(size_t)Mc*NQKV];   // fused QKV output [M][6144]
__device__ half  g_abh [(size_t)Mc*Dc];
__device__ half  g_qh  [(size_t)Mc*Dc];
__device__ half  g_kh  [(size_t)Mc*Dc];
__device__ half  g_vh  [(size_t)Mc*Dc];

// ---------------------------------------------------------------------------
// helpers
// ---------------------------------------------------------------------------
__device__ __forceinline__ uint32_t smem_u32(const void* p) {
    uint32_t a;
    asm("{ .reg .u64 t; cvta.to.shared.u64 t, %1; cvt.u32.u64 %0, t; }"
        : "=r"(a) : "l"(p));
    return a;
}
__device__ __forceinline__ uint32_t pack_h2(float lo, float hi) {
    half2 h = __floats2half2_rn(lo, hi);
    return *(uint32_t*)&h;
}
__device__ __forceinline__ void cp16(uint32_t dst, const void* src) {
    asm volatile("cp.async.cg.shared.global [%0], [%1], 16;" :: "r"(dst), "l"(src));
}
#define CP_COMMIT() asm volatile("cp.async.commit_group;" ::: "memory")
template<int N>
__device__ __forceinline__ void cp_wait() {
    asm volatile("cp.async.wait_group %0;" :: "n"(N) : "memory");
}
__device__ __forceinline__ void ldm_x4(uint32_t r[4], uint32_t addr) {
    asm volatile("ldmatrix.sync.aligned.m8n8.x4.shared.b16 {%0,%1,%2,%3}, [%4];"
        : "=r"(r[0]), "=r"(r[1]), "=r"(r[2]), "=r"(r[3]) : "r"(addr));
}
__device__ __forceinline__ void ldm_x4t(uint32_t r[4], uint32_t addr) {
    asm volatile("ldmatrix.sync.aligned.m8n8.x4.trans.shared.b16 {%0,%1,%2,%3}, [%4];"
        : "=r"(r[0]), "=r"(r[1]), "=r"(r[2]), "=r"(r[3]) : "r"(addr));
}
__device__ __forceinline__ void sts32(uint32_t addr, uint32_t v) {
    asm volatile("st.shared.b32 [%0], %1;" :: "r"(addr), "r"(v));
}
__device__ __forceinline__ void mma_fp16(float c[4], const uint32_t a[4],
                                         const uint32_t b0, const uint32_t b1) {
    asm volatile(
        "mma.sync.aligned.m16n8k16.row.col.f32.f16.f16.f32 "
        "{%0,%1,%2,%3}, {%4,%5,%6,%7}, {%8,%9}, {%0,%1,%2,%3};"
        : "+f"(c[0]), "+f"(c[1]), "+f"(c[2]), "+f"(c[3])
        : "r"(a[0]), "r"(a[1]), "r"(a[2]), "r"(a[3]),
          "r"(b0), "r"(b1));
}

// ---------------------------------------------------------------------------
// fp32 -> fp16 conversion
// ---------------------------------------------------------------------------
__global__ __launch_bounds__(256) void f32_to_f16(
    const float* __restrict__ src, half* __restrict__ dst, int n)
{
    int i = (blockIdx.x * 256 + threadIdx.x) * 8;
    for (; i < n; i += gridDim.x * 256 * 8) {
        float4 a = *(const float4*)(src + i);
        float4 b = *(const float4*)(src + i + 4);
        uint4 u = make_uint4(pack_h2(a.x, a.y), pack_h2(a.z, a.w),
                             pack_h2(b.x, b.y), pack_h2(b.z, b.w));
        *(uint4*)(dst + i) = u;
    }
}

// ---------------------------------------------------------------------------
// fp16 GEMM core: CTA tile 128x256, warp tile 64x64, BK=32, cp.async 3-stage.
// Template on output type (half for QKV path, float for final Wo GEMM).
// Swizzle: 64B rows, 16B chunk c at phys = c ^ ((row>>1)&3).
// ---------------------------------------------------------------------------
#define GBM 128
#define GBN 256
#define GBK 32
#define GA_BUF 8192u
#define GB_BUF 16384u
#define GB_BASE (3u * GA_BUF)
#define GEMM_SMEM (GB_BASE + 3u * GB_BUF)   // 73728
#define STAGES 3

template <typename OutT>
__device__ __forceinline__ void gemm_fp16_body(
    const half* __restrict__ A, const half* __restrict__ W,
    OutT* __restrict__ C, int M, int N, int K)
{
    extern __shared__ half gsm[];
    const uint32_t S0 = smem_u32(gsm);

    const int tid  = threadIdx.x;
    const int warp = tid >> 5, lane = tid & 31;
    const int gid  = lane >> 2, tig = lane & 3;
    const int wm   = (warp >> 2) * 64, wn = (warp & 3) * 64;
    const int bm   = blockIdx.y * GBM,  bn = blockIdx.x * GBN;

    int aRow[2], aC[2]; uint32_t aDst[2];
#pragma unroll
    for (int i = 0; i < 2; i++) {
        int cid = tid + 256 * i;
        aRow[i] = cid >> 2; aC[i] = cid & 3;
        int phys = aC[i] ^ ((aRow[i] >> 1) & 3);
        aDst[i] = S0 + aRow[i] * 64 + phys * 16;
    }
    int bRow[4], bC[4]; uint32_t bDst[4];
#pragma unroll
    for (int i = 0; i < 4; i++) {
        int cid = tid + 256 * i;
        bRow[i] = cid >> 2; bC[i] = cid & 3;
        int phys = bC[i] ^ ((bRow[i] >> 1) & 3);
        bDst[i] = S0 + GB_BASE + bRow[i] * 64 + phys * 16;
    }

    uint32_t arow[4]; int axor[4];
    const int ahi = lane >> 4;
#pragma unroll
    for (int mt = 0; mt < 4; mt++) {
        int r = wm + 16 * mt + (lane & 7) + ((lane >> 3) & 1) * 8;
        arow[mt] = S0 + r * 64;
        axor[mt] = (r >> 1) & 3;
    }
    uint32_t brow[4]; int bxor[4];
    const int bhi = (lane >> 3) & 1;
#pragma unroll
    for (int n2 = 0; n2 < 4; n2++) {
        int r = wn + n2 * 16 + (lane & 7) + ((lane >> 4) & 1) * 8;
        brow[n2] = S0 + GB_BASE + r * 64;
        bxor[n2] = (r >> 1) & 3;
    }

    float acc[4][8][4];
#pragma unroll
    for (int i = 0; i < 4; i++)
#pragma unroll
        for (int j = 0; j < 8; j++)
#pragma unroll
            for (int l = 0; l < 4; l++) acc[i][j][l] = 0.f;

    const int NT = K / GBK;

#pragma unroll
    for (int s = 0; s < 2; s++) {
#pragma unroll
        for (int i = 0; i < 2; i++)
            cp16(aDst[i] + s * GA_BUF,
                 A + (size_t)(bm + aRow[i]) * K + s * GBK + aC[i] * 8);
#pragma unroll
        for (int i = 0; i < 4; i++)
            cp16(bDst[i] + s * GB_BUF,
                 W + (size_t)(bn + bRow[i]) * K + s * GBK + bC[i] * 8);
        CP_COMMIT();
    }

    for (int kt = 0; kt < NT; kt++) {
        if (kt == NT - 1) cp_wait<0>(); else cp_wait<1>();
        __syncthreads();

        if (kt + 2 < NT) {
            const int s = kt + 2;
            const uint32_t sa = (uint32_t)(s % STAGES) * GA_BUF;
            const uint32_t sb = (uint32_t)(s % STAGES) * GB_BUF;
#pragma unroll
            for (int i = 0; i < 2; i++)
                cp16(aDst[i] + sa,
                     A + (size_t)(bm + aRow[i]) * K + s * GBK + aC[i] * 8);
#pragma unroll
            for (int i = 0; i < 4; i++)
                cp16(bDst[i] + sb,
                     W + (size_t)(bn + bRow[i]) * K + s * GBK + bC[i] * 8);
            CP_COMMIT();
        }

        const uint32_t aofs = (uint32_t)(kt % STAGES) * GA_BUF;
        const uint32_t bofs = (uint32_t)(kt % STAGES) * GB_BUF;
#pragma unroll
        for (int ks = 0; ks < 2; ks++) {
            uint32_t af[4][4], bf[8][2];
#pragma unroll
            for (int mt = 0; mt < 4; mt++) {
                int chunk = 2 * ks + ahi;
                ldm_x4(af[mt], arow[mt] + aofs + (uint32_t)((chunk ^ axor[mt]) * 16));
            }
#pragma unroll
            for (int n2 = 0; n2 < 4; n2++) {
                int chunk = 2 * ks + bhi;
                uint32_t r[4];
                ldm_x4(r, brow[n2] + bofs + (uint32_t)((chunk ^ bxor[n2]) * 16));
                bf[n2*2][0] = r[0]; bf[n2*2][1] = r[1];
                bf[n2*2+1][0] = r[2]; bf[n2*2+1][1] = r[3];
            }
#pragma unroll
            for (int mt = 0; mt < 4; mt++)
#pragma unroll
                for (int nt = 0; nt < 8; nt++)
                    mma_fp16(acc[mt][nt], af[mt], bf[nt][0], bf[nt][1]);
        }
    }

    // epilogue
#pragma unroll
    for (int mt = 0; mt < 4; mt++) {
        int r0 = bm + wm + mt * 16 + gid;
#pragma unroll
        for (int nt = 0; nt < 8; nt++) {
            int c0 = bn + wn + nt * 8 + tig * 2;
            if (sizeof(OutT) == 2) {
                half* Ch = (half*)C;
                *(uint32_t*)&Ch[(size_t)r0 * N + c0]       = pack_h2(acc[mt][nt][0], acc[mt][nt][1]);
                *(uint32_t*)&Ch[(size_t)(r0 + 8) * N + c0] = pack_h2(acc[mt][nt][2], acc[mt][nt][3]);
            } else {
                float* Cf = (float*)C;
                *(float2*)&Cf[(size_t)r0 * N + c0]       = make_float2(acc[mt][nt][0], acc[mt][nt][1]);
                *(float2*)&Cf[(size_t)(r0 + 8) * N + c0] = make_float2(acc[mt][nt][2], acc[mt][nt][3]);
            }
        }
    }
}

__global__ __launch_bounds__(256) void gemm_fp16_h(
    const half* __restrict__ A, const half* __restrict__ W,
    half* __restrict__ C, int M, int N, int K)
{ gemm_fp16_body<half>(A, W, C, M, N, K); }

__global__ __launch_bounds__(256) void gemm_fp16_f(
    const half* __restrict__ A, const half* __restrict__ W,
    float* __restrict__ C, int M, int N, int K)
{ gemm_fp16_body<float>(A, W, C, M, N, K); }

// ---------------------------------------------------------------------------
// counts
// ---------------------------------------------------------------------------
__global__ __launch_bounds__(256) void counts_kernel(
    const float* __restrict__ mask, float* __restrict__ cnt)
{
    __shared__ float part[256];
    const int b = blockIdx.x;
    const int t = threadIdx.x;
    const int base = b * Sc;

    float local[8];
    float sum = 0.f;
#pragma unroll
    for (int j = 0; j < 8; j++) {
        int s = t * 8 + j;
        float kp = (mask[base + s] == 0.f) ? 1.f : 0.f;
        sum += kp;
        local[j] = sum;
    }
    part[t] = sum;
    __syncthreads();
    if (t == 0) {
        float run = 0.f;
        for (int i = 0; i < 256; i++) { float tmp = part[i]; part[i] = run; run += tmp; }
    }
    __syncthreads();
    float off = part[t];
#pragma unroll
    for (int j = 0; j < 8; j++)
        cnt[base + t * 8 + j] = off + local[j];
}

// ---------------------------------------------------------------------------
// fused post-projection: reads fused fp16 QKV [M][6144], RoPE+L2norm+mask
// for Q/K, scale V; writes fp16 Q/K/V [M][2048]
// ---------------------------------------------------------------------------
__global__ __launch_bounds__(128) void post_qkv_kernel(
    const half* __restrict__ QKV,
    half* __restrict__ Qh, half* __restrict__ Kh, half* __restrict__ Vh,
    const float* __restrict__ mask, const int* __restrict__ pos,
    const float* __restrict__ cnt, const float* __restrict__ nc)
{
    const int bsh = blockIdx.x;
    const int h  = bsh & (Hc - 1);
    const int bs = bsh >> 4;
    const int d = threadIdx.x;
    const size_t inb = (size_t)bs * NQKV + h * HDc + d;
    const size_t outb = (size_t)bs * Dc + h * HDc + d;

    __shared__ float sq[HDc], sk[HDc];
    __shared__ float redq[4], redk[4];

    float xq = __half2float(QKV[inb]);
    float xk = __half2float(QKV[inb + Dc]);
    float xv = __half2float(QKV[inb + 2 * Dc]);
    sq[d] = xq; sk[d] = xk;
    __syncthreads();

    float yq = xq, yk = xk;
    if (d < ROTc) {
        int i = d >> 1;
        float inv = powf(10000.f, -(float)(2 * i) / (float)ROTc);
        float ang = (float)pos[bs] * inv;
        float sn, cs;
        sincosf(ang, &sn, &cs);
        float oq = (d & 1) ? sq[d - 1] : sq[d + 1];
        float ok = (d & 1) ? sk[d - 1] : sk[d + 1];
        yq = (d & 1) ? (xq * cs + oq * sn) : (xq * cs - oq * sn);
        yk = (d & 1) ? (xk * cs + ok * sn) : (xk * cs - ok * sn);
    }

    float ssq = yq * yq, ssk = yk * yk;
#pragma unroll
    for (int o = 16; o; o >>= 1) {
        ssq += __shfl_xor_sync(0xffffffffu, ssq, o);
        ssk += __shfl_xor_sync(0xffffffffu, ssk, o);
    }
    if ((d & 31) == 0) { redq[d >> 5] = ssq; redk[d >> 5] = ssk; }
    __syncthreads();
    float nq = sqrtf(redq[0] + redq[1] + redq[2] + redq[3]);
    float nk = sqrtf(redk[0] + redk[1] + redk[2] + redk[3]);

    float keep = (mask[bs] == 0.f) ? 1.f : 0.f;
    Qh[outb] = __float2half(yq / fmaxf(nq, 1e-12f) * keep);
    Kh[outb] = __float2half(yk / fmaxf(nk, 1e-12f) * keep);

    float expo = 1.f / (1.f + expf(-nc[h]));
    float scale = keep / fmaxf(powf(cnt[bs], expo), 1.f);
    Vh[outb] = __float2half(xv * scale);
}

// ---------------------------------------------------------------------------
// fp16 tensor-core causal attention (unchanged from R8/R9)
// ---------------------------------------------------------------------------
#define AQ2 64
#define ATT_QS 0u
#define ATT_KS0 16384u
#define ATT_KS1 32768u
#define ATT_VS0 49152u
#define ATT_VS1 65536u
#define ATT_PS 81920u
#define ATT_SMEM 90112

__global__ __launch_bounds__(256) void attn_fp16(
    const half* __restrict__ Qh, const half* __restrict__ Kh,
    const half* __restrict__ Vh, half* __restrict__ O)
{
    extern __shared__ half smh[];
    const uint32_t S0 = smem_u32(smh);

    const int bh = blockIdx.y;
    const int b = bh >> 4;
    const int h = bh & (Hc - 1);
    const int qt = blockIdx.x;

    const int tid  = threadIdx.x;
    const int warp = tid >> 5, lane = tid & 31;
    const int gid  = lane >> 2, tig = lane & 3;
    const int wq   = (warp >> 1) * 16;
    const int wk   = (warp & 1) * 32;
    const int wd   = (warp & 1) * 64;

    const uint32_t kbuf[2] = {ATT_KS0, ATT_KS1};
    const uint32_t vbuf[2] = {ATT_VS0, ATT_VS1};

    int srow[4], sphy[4];
#pragma unroll
    for (int i = 0; i < 4; i++) {
        int cid = tid + 256 * i;
        srow[i] = cid >> 4;
        int c = cid & 15;
        sphy[i] = c ^ (srow[i] & 7);
    }

    const half* Qg = Qh + ((size_t)(b * Sc + qt * AQ2)) * Dc + h * HDc;

#pragma unroll
    for (int i = 0; i < 4; i++) {
        int c = (tid + 256 * i) & 15;
        cp16(S0 + ATT_QS + srow[i] * 256 + sphy[i] * 16,
             Qg + (size_t)srow[i] * Dc + c * 8);
    }
    {
        const half* Kg = Kh + ((size_t)(b * Sc)) * Dc + h * HDc;
        const half* Vg = Vh + ((size_t)(b * Sc)) * Dc + h * HDc;
#pragma unroll
        for (int i = 0; i < 4; i++) {
            int c = (tid + 256 * i) & 15;
            cp16(S0 + kbuf[0] + srow[i] * 256 + sphy[i] * 16,
                 Kg + (size_t)srow[i] * Dc + c * 8);
            cp16(S0 + vbuf[0] + srow[i] * 256 + sphy[i] * 16,
                 Vg + (size_t)srow[i] * Dc + c * 8);
        }
    }
    CP_COMMIT();

    float oacc[8][4];
#pragma unroll
    for (int i = 0; i < 8; i++)
#pragma unroll
        for (int l = 0; l < 4; l++) oacc[i][l] = 0.f;

    const int arow1 = wq + (lane & 7) + ((lane >> 3) & 1) * 8;
    const int ax1 = arow1 & 7;
    const int chi = lane >> 4;

    for (int kt = 0; kt <= qt; kt++) {
        cp_wait<0>();
        __syncthreads();

        if (kt + 1 <= qt) {
            const int s = kt + 1;
            const uint32_t kb = kbuf[s & 1], vb = vbuf[s & 1];
            const half* Kg = Kh + ((size_t)(b * Sc + s * AQ2)) * Dc + h * HDc;
            const half* Vg = Vh + ((size_t)(b * Sc + s * AQ2)) * Dc + h * HDc;
#pragma unroll
            for (int i = 0; i < 4; i++) {
                int c = (tid + 256 * i) & 15;
                cp16(S0 + kb + srow[i] * 256 + sphy[i] * 16,
                     Kg + (size_t)srow[i] * Dc + c * 8);
                cp16(S0 + vb + srow[i] * 256 + sphy[i] * 16,
                     Vg + (size_t)srow[i] * Dc + c * 8);
            }
            CP_COMMIT();
        }

        const uint32_t kbs = S0 + kbuf[kt & 1];
        const uint32_t vbs = S0 + vbuf[kt & 1];

        float pacc[4][4];
#pragma unroll
        for (int i = 0; i < 4; i++)
#pragma unroll
            for (int l = 0; l < 4; l++) pacc[i][l] = 0.f;

#pragma unroll
        for (int ks = 0; ks < 8; ks++) {
            const int c0 = ks * 2 + chi;
            uint32_t a[4];
            ldm_x4(a, S0 + ATT_QS + arow1 * 256 + ((c0 ^ ax1) * 16));
#pragma unroll
            for (int n2 = 0; n2 < 2; n2++) {
                int brow = wk + n2 * 16 + (lane & 7) + ((lane >> 3) & 1) * 8;
                uint32_t r[4];
                ldm_x4(r, kbs + brow * 256 + ((c0 ^ (brow & 7)) * 16));
                mma_fp16(pacc[2*n2],   a, r[0], r[2]);
                mma_fp16(pacc[2*n2+1], a, r[1], r[3]);
            }
        }

        const bool diag = (kt == qt);
#pragma unroll
        for (int nt = 0; nt < 4; nt++) {
            int kl0 = wk + nt * 8 + tig * 2;
            int q0 = wq + gid, q1 = q0 + 8;
            float v00 = pacc[nt][0], v01 = pacc[nt][1];
            float v10 = pacc[nt][2], v11 = pacc[nt][3];
            if (diag) {
                if (kl0     > q0) v00 = 0.f;
                if (kl0 + 1 > q0) v01 = 0.f;
                if (kl0     > q1) v10 = 0.f;
                if (kl0 + 1 > q1) v11 = 0.f;
            }
            int chunk = kl0 >> 3;
            sts32(S0 + ATT_PS + q0 * 128 + ((chunk ^ (q0 & 7)) * 16) + tig * 4,
                  pack_h2(v00, v01));
            sts32(S0 + ATT_PS + q1 * 128 + ((chunk ^ (q1 & 7)) * 16) + tig * 4,
                  pack_h2(v10, v11));
        }
        __syncthreads();

#pragma unroll
        for (int ks = 0; ks < 4; ks++) {
            const int ca = ks * 2 + chi;
            uint32_t a[4];
            ldm_x4(a, S0 + ATT_PS + arow1 * 128 + ((ca ^ ax1) * 16));
            const int vrow = ks * 16 + (lane & 7) + ((lane >> 3) & 1) * 8;
            const int vx = vrow & 7;
#pragma unroll
            for (int j = 0; j < 4; j++) {
                int cd = (wd >> 3) + j * 2 + chi;
                uint32_t r[4];
                ldm_x4t(r, vbs + vrow * 256 + ((cd ^ vx) * 16));
                mma_fp16(oacc[2*j],   a, r[0], r[1]);
                mma_fp16(oacc[2*j+1], a, r[2], r[3]);
            }
        }
        __syncthreads();
    }

    half* Og = O + ((size_t)(b * Sc + qt * AQ2)) * Dc + h * HDc;
    int q0 = wq + gid, q1 = q0 + 8;
#pragma unroll
    for (int nt = 0; nt < 8; nt++) {
        int d0 = wd + nt * 8 + tig * 2;
        *(uint32_t*)&Og[(size_t)q0 * Dc + d0] = pack_h2(oacc[nt][0], oacc[nt][1]);
        *(uint32_t*)&Og[(size_t)q1 * Dc + d0] = pack_h2(oacc[nt][2], oacc[nt][3]);
    }
}

// ---------------------------------------------------------------------------
// launch
// ---------------------------------------------------------------------------
extern "C" void kernel_launch(void* const* d_in, const int* in_sizes, int n_in,
                              void* d_out, int out_size)
{
    const float* hs   = (const float*)d_in[0];
    const float* mask = (const float*)d_in[1];
    const int*   pos  = (const int*)  d_in[2];
    const float* Wq   = (const float*)d_in[3];
    const float* Wk   = (const float*)d_in[4];
    const float* Wv   = (const float*)d_in[5];
    const float* Wo   = (const float*)d_in[6];
    const float* nc   = (const float*)d_in[7];
    float* out = (float*)d_out;

    float *cnt;
    half *hsh, *wh, *woh, *qkvh, *abh, *qh, *kh, *vh;
    cudaGetSymbolAddress((void**)&cnt,  g_cnt);
    cudaGetSymbolAddress((void**)&hsh,  g_hsh);
    cudaGetSymbolAddress((void**)&wh,   g_wh);
    cudaGetSymbolAddress((void**)&woh,  g_woh);
    cudaGetSymbolAddress((void**)&qkvh, g_qkvh);
    cudaGetSymbolAddress((void**)&abh,  g_abh);
    cudaGetSymbolAddress((void**)&qh,   g_qh);
    cudaGetSymbolAddress((void**)&kh,   g_kh);
    cudaGetSymbolAddress((void**)&vh,   g_vh);

    cudaFuncSetAttribute(gemm_fp16_h,
                         cudaFuncAttributeMaxDynamicSharedMemorySize, GEMM_SMEM);
    cudaFuncSetAttribute(gemm_fp16_f,
                         cudaFuncAttributeMaxDynamicSharedMemorySize, GEMM_SMEM);
    cudaFuncSetAttribute(attn_fp16,
                         cudaFuncAttributeMaxDynamicSharedMemorySize, ATT_SMEM);

    const int nHS = Mc * Dc;
    const int nW  = Dc * Dc;

    counts_kernel<<<Bc, 256>>>(mask, cnt);

    f32_to_f16<<<nHS / (256 * 8), 256>>>(hs, hsh, nHS);
    f32_to_f16<<<nW  / (256 * 8), 256>>>(Wq, wh, nW);
    f32_to_f16<<<nW  / (256 * 8), 256>>>(Wk, wh + (size_t)Dc * Dc, nW);
    f32_to_f16<<<nW  / (256 * 8), 256>>>(Wv, wh + (size_t)2 * Dc * Dc, nW);
    f32_to_f16<<<nW  / (256 * 8), 256>>>(Wo, woh, nW);

    // fused QKV GEMM: [M][2048] x [6144][2048]^T -> [M][6144] fp16
    dim3 qkvGrid(NQKV / GBN, Mc / GBM);   // (24, 32)
    gemm_fp16_h<<<qkvGrid, 256, GEMM_SMEM>>>(hsh, wh, qkvh, Mc, NQKV, Dc);

    const int nrows = Bc * Sc * Hc;
    post_qkv_kernel<<<nrows, 128>>>(qkvh, qh, kh, vh, mask, pos, cnt, nc);

    dim3 attnGrid(Sc / AQ2, Bc * Hc);     // (32, 32)
    attn_fp16<<<attnGrid, 256, ATT_SMEM>>>(qh, kh, vh, abh);

    dim3 oGrid(Dc / GBN, Mc / GBM);       // (8, 32)
    gemm_fp16_f<<<oGrid, 256, GEMM_SMEM>>>(abh, woh, out, Mc, Dc, Dc);
}